// round 3
// baseline (speedup 1.0000x reference)
#include <cuda_runtime.h>
#include <math.h>

#define NMAX 50000
#define EMAX 800000
#define ETOTMAX (EMAX + NMAX)
#define GMAX 64
#define LN_EPS 1e-5f
#define SLOPE 0.2f

// ---------------- scratch (static device globals; no runtime alloc) ----------
__device__ float g_h   [(size_t)NMAX * 256];   // GEMM output (pre-aggregation features)
__device__ float g_agg [(size_t)NMAX * 256];   // aggregation accumulator
__device__ float g_in  [(size_t)NMAX * 256];   // normalized features (input to next layer)
__device__ float g_e   [(size_t)ETOTMAX * 4];  // per-edge score -> prob
__device__ float g_esrc[NMAX * 4];
__device__ float g_edst[NMAX * 4];
__device__ float g_m   [NMAX * 4];
__device__ float g_den [NMAX * 4];
__device__ float g_gsum[GMAX * 128];
__device__ int   g_cnt [GMAX];

// ---------------- helpers ----------------------------------------------------
__device__ __forceinline__ void atomicMaxF(float* addr, float v) {
    // monotone-upward float max via int/uint ordering trick
    if (v >= 0.f) atomicMax((int*)addr, __float_as_int(v));
    else          atomicMin((unsigned int*)addr, __float_as_uint(v));
}

__global__ void zero_f4(float4* p, int n4) {
    int i = blockIdx.x * blockDim.x + threadIdx.x;
    if (i < n4) p[i] = make_float4(0.f, 0.f, 0.f, 0.f);
}

// ---------------- SGEMM 128x128x16, 256 threads, 8x8 microtile ---------------
__global__ void sgemm_kernel(const float* __restrict__ A, const float* __restrict__ B,
                             float* __restrict__ C, int M, int K, int N) {
    __shared__ float As[16][128];   // transposed: As[k][m]
    __shared__ float Bs[16][128];

    int tid = threadIdx.x;
    int bm = blockIdx.y * 128;
    int bn = blockIdx.x * 128;
    int tx = tid & 15;       // 16 cols of threads
    int ty = tid >> 4;       // 16 rows of threads

    float acc[8][8];
#pragma unroll
    for (int i = 0; i < 8; i++)
#pragma unroll
        for (int j = 0; j < 8; j++) acc[i][j] = 0.f;

    for (int k0 = 0; k0 < K; k0 += 16) {
        // load A tile 128x16 (512 float4), store transposed
#pragma unroll
        for (int l = 0; l < 2; l++) {
            int i = tid + l * 256;
            int r = i >> 2;
            int c4 = (i & 3) * 4;
            float4 v = make_float4(0.f, 0.f, 0.f, 0.f);
            int gr = bm + r;
            if (gr < M) v = *(const float4*)(A + (size_t)gr * K + k0 + c4);
            As[c4 + 0][r] = v.x;
            As[c4 + 1][r] = v.y;
            As[c4 + 2][r] = v.z;
            As[c4 + 3][r] = v.w;
        }
        // load B tile 16x128 (512 float4)
#pragma unroll
        for (int l = 0; l < 2; l++) {
            int i = tid + l * 256;
            int r = i >> 5;
            int c = (i & 31) * 4;
            float4 v = *(const float4*)(B + (size_t)(k0 + r) * N + bn + c);
            *(float4*)&Bs[r][c] = v;
        }
        __syncthreads();

#pragma unroll
        for (int k = 0; k < 16; k++) {
            float4 a0 = *(const float4*)&As[k][ty * 8];
            float4 a1 = *(const float4*)&As[k][ty * 8 + 4];
            float4 b0 = *(const float4*)&Bs[k][tx * 8];
            float4 b1 = *(const float4*)&Bs[k][tx * 8 + 4];
            float a[8] = {a0.x, a0.y, a0.z, a0.w, a1.x, a1.y, a1.z, a1.w};
            float b[8] = {b0.x, b0.y, b0.z, b0.w, b1.x, b1.y, b1.z, b1.w};
#pragma unroll
            for (int i = 0; i < 8; i++)
#pragma unroll
                for (int j = 0; j < 8; j++) acc[i][j] += a[i] * b[j];
        }
        __syncthreads();
    }

#pragma unroll
    for (int i = 0; i < 8; i++) {
        int gr = bm + ty * 8 + i;
        if (gr < M) {
            float4 v0 = make_float4(acc[i][0], acc[i][1], acc[i][2], acc[i][3]);
            float4 v1 = make_float4(acc[i][4], acc[i][5], acc[i][6], acc[i][7]);
            *(float4*)(C + (size_t)gr * N + bn + tx * 8)     = v0;
            *(float4*)(C + (size_t)gr * N + bn + tx * 8 + 4) = v1;
        }
    }
}

// ---------------- per-(node,head) attention scores + init --------------------
__global__ void scores_kernel(const float* __restrict__ h,
                              const float* __restrict__ asrc, const float* __restrict__ adst,
                              float* __restrict__ esrc, float* __restrict__ edst,
                              float* __restrict__ m, float* __restrict__ den,
                              int Nn, int C) {
    int i = blockIdx.x * blockDim.x + threadIdx.x;  // n*4 + head
    if (i >= Nn * 4) return;
    int n = i >> 2, hd = i & 3;
    const float* hp = h + (size_t)n * (4 * C) + hd * C;
    const float* as = asrc + hd * C;
    const float* ad = adst + hd * C;
    float s1 = 0.f, s2 = 0.f;
    for (int c = 0; c < C; c++) {
        float v = hp[c];
        s1 += v * as[c];
        s2 += v * ad[c];
    }
    esrc[i] = s1;
    edst[i] = s2;
    m[i] = -INFINITY;
    den[i] = 0.f;
}

// ---------------- edge pass 1: leaky-relu score + segment max ----------------
__global__ void edge_max_kernel(const float* __restrict__ esrc, const float* __restrict__ edst,
                                float* __restrict__ m, float* __restrict__ ge,
                                const int* __restrict__ src, const int* __restrict__ dst,
                                int E_, int Etot) {
    int e = blockIdx.x * blockDim.x + threadIdx.x;
    if (e >= Etot) return;
    int s, d;
    if (e < E_) { s = src[e]; d = dst[e]; } else { s = d = e - E_; }
    float4 a = ((const float4*)esrc)[s];
    float4 b = ((const float4*)edst)[d];
    float v0 = a.x + b.x; v0 = v0 > 0.f ? v0 : SLOPE * v0;
    float v1 = a.y + b.y; v1 = v1 > 0.f ? v1 : SLOPE * v1;
    float v2 = a.z + b.z; v2 = v2 > 0.f ? v2 : SLOPE * v2;
    float v3 = a.w + b.w; v3 = v3 > 0.f ? v3 : SLOPE * v3;
    ((float4*)ge)[e] = make_float4(v0, v1, v2, v3);
    atomicMaxF(&m[d * 4 + 0], v0);
    atomicMaxF(&m[d * 4 + 1], v1);
    atomicMaxF(&m[d * 4 + 2], v2);
    atomicMaxF(&m[d * 4 + 3], v3);
}

// ---------------- edge pass 2: exp + denominator -----------------------------
__global__ void edge_den_kernel(float* __restrict__ ge, const float* __restrict__ m,
                                float* __restrict__ den,
                                const int* __restrict__ dst, int E_, int Etot) {
    int e = blockIdx.x * blockDim.x + threadIdx.x;
    if (e >= Etot) return;
    int d = (e < E_) ? dst[e] : (e - E_);
    float4 v = ((float4*)ge)[e];
    float4 mm = ((const float4*)m)[d];
    float p0 = expf(v.x - mm.x);
    float p1 = expf(v.y - mm.y);
    float p2 = expf(v.z - mm.z);
    float p3 = expf(v.w - mm.w);
    ((float4*)ge)[e] = make_float4(p0, p1, p2, p3);
    atomicAdd(&den[d * 4 + 0], p0);
    atomicAdd(&den[d * 4 + 1], p1);
    atomicAdd(&den[d * 4 + 2], p2);
    atomicAdd(&den[d * 4 + 3], p3);
}

// ---------------- edge pass 3: scatter alpha * h[src] (warp per edge) --------
__global__ void edge_scatter_kernel(const float* __restrict__ hfeat, float* __restrict__ agg,
                                    const float* __restrict__ ge, const float* __restrict__ den,
                                    const int* __restrict__ src, const int* __restrict__ dst,
                                    int E_, int Etot, int HC, int logC) {
    int wid = (blockIdx.x * blockDim.x + threadIdx.x) >> 5;
    int lane = threadIdx.x & 31;
    if (wid >= Etot) return;
    int s, d;
    if (wid < E_) { s = src[wid]; d = dst[wid]; } else { s = d = wid - E_; }
    float alpha[4];
#pragma unroll
    for (int h = 0; h < 4; h++) alpha[h] = ge[wid * 4 + h] / den[d * 4 + h];
    const float* hs = hfeat + (size_t)s * HC;
    float* ad = agg + (size_t)d * HC;
    for (int f = lane; f < HC; f += 32) {
        atomicAdd(ad + f, alpha[f >> logC] * hs[f]);
    }
}

// ---------------- epilogue: bias (+ELU) + LayerNorm (+pool) ------------------
__global__ void epilogue_kernel(const float* __restrict__ agg, const float* __restrict__ bias,
                                const float* __restrict__ gam, const float* __restrict__ bet,
                                float* __restrict__ outp, int HC, int doElu, int doPool,
                                const int* __restrict__ batch,
                                float* __restrict__ gsum, int* __restrict__ cnt) {
    __shared__ float red[256];
    int n = blockIdx.x;
    int f = threadIdx.x;
    float v = agg[(size_t)n * HC + f] + bias[f];
    if (doElu) v = v > 0.f ? v : expm1f(v);

    red[f] = v;
    __syncthreads();
    for (int s = HC >> 1; s > 0; s >>= 1) {
        if (f < s) red[f] += red[f + s];
        __syncthreads();
    }
    float mu = red[0] / (float)HC;
    __syncthreads();
    float dv = v - mu;
    red[f] = dv * dv;
    __syncthreads();
    for (int s = HC >> 1; s > 0; s >>= 1) {
        if (f < s) red[f] += red[f + s];
        __syncthreads();
    }
    float var = red[0] / (float)HC;
    float y = gam[f] * dv * rsqrtf(var + LN_EPS) + bet[f];
    outp[(size_t)n * HC + f] = y;

    if (doPool) {
        int b = batch[n];
        atomicAdd(&gsum[b * HC + f], y);
        if (f == 0) atomicAdd(&cnt[b], 1);
    }
}

__global__ void pool_finalize_kernel(float* __restrict__ graph_out,
                                     const float* __restrict__ gsum,
                                     const int* __restrict__ cnt) {
    int i = blockIdx.x * blockDim.x + threadIdx.x;
    if (i < GMAX * 128) {
        graph_out[i] = gsum[i] / fmaxf((float)cnt[i >> 7], 1.f);
    }
}

// ---------------- launch -----------------------------------------------------
extern "C" void kernel_launch(void* const* d_in, const int* in_sizes, int n_in,
                              void* d_out, int out_size) {
    const float* x     = (const float*)d_in[0];
    const int*   ei    = (const int*)d_in[1];
    const int*   batch = (const int*)d_in[2];
    const float* W[3]    = {(const float*)d_in[3],  (const float*)d_in[9],  (const float*)d_in[15]};
    const float* asrc[3] = {(const float*)d_in[4],  (const float*)d_in[10], (const float*)d_in[16]};
    const float* adst[3] = {(const float*)d_in[5],  (const float*)d_in[11], (const float*)d_in[17]};
    const float* bia[3]  = {(const float*)d_in[6],  (const float*)d_in[12], (const float*)d_in[18]};
    const float* gam[3]  = {(const float*)d_in[7],  (const float*)d_in[13], (const float*)d_in[19]};
    const float* bet[3]  = {(const float*)d_in[8],  (const float*)d_in[14], (const float*)d_in[20]};

    int N = in_sizes[0] / 768;
    int E = in_sizes[1] / 2;
    int Etot = E + N;
    const int* srcA = ei;
    const int* dstA = ei + E;

    float* node_out  = (float*)d_out;
    float* graph_out = node_out + (size_t)N * 128;

    float *p_h, *p_agg, *p_in, *p_e, *p_esrc, *p_edst, *p_m, *p_den, *p_gsum;
    int* p_cnt;
    cudaGetSymbolAddress((void**)&p_h, g_h);
    cudaGetSymbolAddress((void**)&p_agg, g_agg);
    cudaGetSymbolAddress((void**)&p_in, g_in);
    cudaGetSymbolAddress((void**)&p_e, g_e);
    cudaGetSymbolAddress((void**)&p_esrc, g_esrc);
    cudaGetSymbolAddress((void**)&p_edst, g_edst);
    cudaGetSymbolAddress((void**)&p_m, g_m);
    cudaGetSymbolAddress((void**)&p_den, g_den);
    cudaGetSymbolAddress((void**)&p_gsum, g_gsum);
    cudaGetSymbolAddress((void**)&p_cnt, g_cnt);

    // zero pooling accumulators
    zero_f4<<<(GMAX * 128 / 4 + 255) / 256, 256>>>((float4*)p_gsum, GMAX * 128 / 4);
    zero_f4<<<1, 32>>>((float4*)p_cnt, GMAX / 4);

    int dins[3] = {768, 256, 256};
    int HCs[3]  = {256, 256, 128};
    const float* inputs[3] = {x, p_in, p_in};
    float* outs[3] = {p_in, p_in, node_out};

    for (int L = 0; L < 3; L++) {
        int K = dins[L], HC = HCs[L], C = HC / 4;
        int logC = (C == 64) ? 6 : 5;

        dim3 ggrid(HC / 128, (N + 127) / 128);
        sgemm_kernel<<<ggrid, 256>>>(inputs[L], W[L], p_h, N, K, HC);

        scores_kernel<<<(N * 4 + 255) / 256, 256>>>(p_h, asrc[L], adst[L],
                                                    p_esrc, p_edst, p_m, p_den, N, C);

        int n4 = N * HC / 4;
        zero_f4<<<(n4 + 255) / 256, 256>>>((float4*)p_agg, n4);

        edge_max_kernel<<<(Etot + 255) / 256, 256>>>(p_esrc, p_edst, p_m, p_e,
                                                     srcA, dstA, E, Etot);
        edge_den_kernel<<<(Etot + 255) / 256, 256>>>(p_e, p_m, p_den, dstA, E, Etot);

        int nthr = Etot * 32;
        edge_scatter_kernel<<<(nthr + 255) / 256, 256>>>(p_h, p_agg, p_e, p_den,
                                                         srcA, dstA, E, Etot, HC, logC);

        epilogue_kernel<<<N, HC>>>(p_agg, bia[L], gam[L], bet[L], outs[L],
                                   HC, (L < 2) ? 1 : 0, (L == 2) ? 1 : 0,
                                   batch, p_gsum, p_cnt);
    }

    pool_finalize_kernel<<<(GMAX * 128 + 127) / 128, 128>>>(graph_out, p_gsum, p_cnt);
}

// round 4
// speedup vs baseline: 1.6357x; 1.6357x over previous
#include <cuda_runtime.h>
#include <math.h>

#define NMAX 50000
#define EMAX 800000
#define ETOTMAX (EMAX + NMAX)
#define GMAX 64
#define LN_EPS 1e-5f
#define SLOPE 0.2f

// ---------------- scratch (static device globals; no runtime alloc) ----------
__device__ float g_h   [(size_t)NMAX * 256];   // GEMM output (pre-aggregation features)
__device__ float g_in  [(size_t)NMAX * 256];   // normalized features (input to next layer)
__device__ float g_esrc[NMAX * 4];
__device__ float g_edst[NMAX * 4];
__device__ int   g_deg [NMAX + 1];
__device__ int   g_off [NMAX + 1];
__device__ int   g_cur [NMAX];
__device__ int   g_csr [ETOTMAX];

// ---------------- CSR build --------------------------------------------------
__global__ void init_deg_kernel(int* __restrict__ deg, int* __restrict__ cur, int Nn) {
    int i = blockIdx.x * blockDim.x + threadIdx.x;
    if (i < Nn) { deg[i] = 1; cur[i] = 0; }   // deg starts at 1: self-loop
}

__global__ void deg_hist_kernel(const int* __restrict__ dst, int E_, int* __restrict__ deg) {
    int i = blockIdx.x * blockDim.x + threadIdx.x;
    if (i < E_) atomicAdd(&deg[dst[i]], 1);
}

// single-block exclusive scan over n ints (n up to 64k): warp-scan + carry loop
__global__ void scan_kernel(const int* __restrict__ deg, int* __restrict__ off, int n) {
    __shared__ int warp_sums[32];
    __shared__ int s_carry;
    int tid = threadIdx.x;           // 1024 threads
    int lane = tid & 31, wid = tid >> 5;
    if (tid == 0) s_carry = 0;
    __syncthreads();
    for (int base = 0; base < n; base += 1024) {
        int idx = base + tid;
        int v = (idx < n) ? deg[idx] : 0;
        int incl = v;
#pragma unroll
        for (int d = 1; d < 32; d <<= 1) {
            int t = __shfl_up_sync(0xffffffffu, incl, d);
            if (lane >= d) incl += t;
        }
        if (lane == 31) warp_sums[wid] = incl;
        __syncthreads();
        if (wid == 0) {
            int ws = warp_sums[lane];
            int wincl = ws;
#pragma unroll
            for (int d = 1; d < 32; d <<= 1) {
                int t = __shfl_up_sync(0xffffffffu, wincl, d);
                if (lane >= d) wincl += t;
            }
            warp_sums[lane] = wincl - ws;   // exclusive prefix of warp sums
        }
        __syncthreads();
        int carry = s_carry;
        if (idx < n) off[idx] = carry + warp_sums[wid] + incl - v;
        __syncthreads();
        if (tid == 1023) s_carry = carry + warp_sums[31] + incl;
        __syncthreads();
    }
    if (tid == 0) off[n] = s_carry;
}

__global__ void csr_scatter_kernel(const int* __restrict__ src, const int* __restrict__ dst,
                                   int E_, int Etot,
                                   const int* __restrict__ off, int* __restrict__ cur,
                                   int* __restrict__ csr_src) {
    int i = blockIdx.x * blockDim.x + threadIdx.x;
    if (i >= Etot) return;
    int s, d;
    if (i < E_) { s = src[i]; d = dst[i]; } else { s = d = i - E_; }
    int pos = off[d] + atomicAdd(&cur[d], 1);
    csr_src[pos] = s;
}

// ---------------- SGEMM 128x128x16, 256 threads, 8x8 microtile ---------------
__global__ void sgemm_kernel(const float* __restrict__ A, const float* __restrict__ B,
                             float* __restrict__ C, int M, int K, int N) {
    __shared__ float As[16][128];
    __shared__ float Bs[16][128];

    int tid = threadIdx.x;
    int bm = blockIdx.y * 128;
    int bn = blockIdx.x * 128;
    int tx = tid & 15;
    int ty = tid >> 4;

    float acc[8][8];
#pragma unroll
    for (int i = 0; i < 8; i++)
#pragma unroll
        for (int j = 0; j < 8; j++) acc[i][j] = 0.f;

    for (int k0 = 0; k0 < K; k0 += 16) {
#pragma unroll
        for (int l = 0; l < 2; l++) {
            int i = tid + l * 256;
            int r = i >> 2;
            int c4 = (i & 3) * 4;
            float4 v = make_float4(0.f, 0.f, 0.f, 0.f);
            int gr = bm + r;
            if (gr < M) v = *(const float4*)(A + (size_t)gr * K + k0 + c4);
            As[c4 + 0][r] = v.x;
            As[c4 + 1][r] = v.y;
            As[c4 + 2][r] = v.z;
            As[c4 + 3][r] = v.w;
        }
#pragma unroll
        for (int l = 0; l < 2; l++) {
            int i = tid + l * 256;
            int r = i >> 5;
            int c = (i & 31) * 4;
            float4 v = *(const float4*)(B + (size_t)(k0 + r) * N + bn + c);
            *(float4*)&Bs[r][c] = v;
        }
        __syncthreads();

#pragma unroll
        for (int k = 0; k < 16; k++) {
            float4 a0 = *(const float4*)&As[k][ty * 8];
            float4 a1 = *(const float4*)&As[k][ty * 8 + 4];
            float4 b0 = *(const float4*)&Bs[k][tx * 8];
            float4 b1 = *(const float4*)&Bs[k][tx * 8 + 4];
            float a[8] = {a0.x, a0.y, a0.z, a0.w, a1.x, a1.y, a1.z, a1.w};
            float b[8] = {b0.x, b0.y, b0.z, b0.w, b1.x, b1.y, b1.z, b1.w};
#pragma unroll
            for (int i = 0; i < 8; i++)
#pragma unroll
                for (int j = 0; j < 8; j++) acc[i][j] += a[i] * b[j];
        }
        __syncthreads();
    }

#pragma unroll
    for (int i = 0; i < 8; i++) {
        int gr = bm + ty * 8 + i;
        if (gr < M) {
            float4 v0 = make_float4(acc[i][0], acc[i][1], acc[i][2], acc[i][3]);
            float4 v1 = make_float4(acc[i][4], acc[i][5], acc[i][6], acc[i][7]);
            *(float4*)(C + (size_t)gr * N + bn + tx * 8)     = v0;
            *(float4*)(C + (size_t)gr * N + bn + tx * 8 + 4) = v1;
        }
    }
}

// ---------------- attention scores: warp per node, coalesced -----------------
// asrc/adst are [H, C] flattened = [HC]; feature f belongs to head f/C, and
// asrc[head][f - head*C] == asrc_flat[f].
template<int RJ, int HS>
__global__ void scores_warp_kernel(const float* __restrict__ h,
                                   const float* __restrict__ asrc, const float* __restrict__ adst,
                                   float* __restrict__ esrc, float* __restrict__ edst, int Nn) {
    const int HC = RJ * 32;
    int warp = (blockIdx.x * blockDim.x + threadIdx.x) >> 5;
    int lane = threadIdx.x & 31;
    if (warp >= Nn) return;
    float ps[4] = {0.f, 0.f, 0.f, 0.f};
    float pd[4] = {0.f, 0.f, 0.f, 0.f};
#pragma unroll
    for (int j = 0; j < RJ; j++) {
        int f = lane + 32 * j;
        float v = h[(size_t)warp * HC + f];
        int hd = j >> HS;
        ps[hd] += v * asrc[f];
        pd[hd] += v * adst[f];
    }
#pragma unroll
    for (int hd = 0; hd < 4; hd++) {
#pragma unroll
        for (int d = 16; d > 0; d >>= 1) {
            ps[hd] += __shfl_xor_sync(0xffffffffu, ps[hd], d);
            pd[hd] += __shfl_xor_sync(0xffffffffu, pd[hd], d);
        }
    }
    if (lane < 4) {
        esrc[warp * 4 + lane] = ps[lane];
        edst[warp * 4 + lane] = pd[lane];
    }
}

// ---------------- fully fused aggregation: warp per dst node -----------------
// softmax-max, exp/denominator, weighted gather of h[src], /denom, +bias,
// (ELU), LayerNorm — all in registers, zero atomics.
template<int RJ, int HS, int DOELU>
__global__ void gat_agg_kernel(const float* __restrict__ hfeat,
                               const float* __restrict__ esrc, const float* __restrict__ edst,
                               const int* __restrict__ off, const int* __restrict__ csr_src,
                               const float* __restrict__ bias,
                               const float* __restrict__ gam, const float* __restrict__ bet,
                               float* __restrict__ outp, int Nn) {
    const int HC = RJ * 32;
    int n = (blockIdx.x * blockDim.x + threadIdx.x) >> 5;
    int lane = threadIdx.x & 31;
    if (n >= Nn) return;

    int beg = off[n], end = off[n + 1];
    float4 ed = ((const float4*)edst)[n];

    // pass 1: segment max per head
    float m0 = -INFINITY, m1 = -INFINITY, m2 = -INFINITY, m3 = -INFINITY;
    for (int i = beg + lane; i < end; i += 32) {
        int s = csr_src[i];
        float4 es = ((const float4*)esrc)[s];
        float e0 = es.x + ed.x; e0 = e0 > 0.f ? e0 : SLOPE * e0; m0 = fmaxf(m0, e0);
        float e1 = es.y + ed.y; e1 = e1 > 0.f ? e1 : SLOPE * e1; m1 = fmaxf(m1, e1);
        float e2 = es.z + ed.z; e2 = e2 > 0.f ? e2 : SLOPE * e2; m2 = fmaxf(m2, e2);
        float e3 = es.w + ed.w; e3 = e3 > 0.f ? e3 : SLOPE * e3; m3 = fmaxf(m3, e3);
    }
#pragma unroll
    for (int d = 16; d > 0; d >>= 1) {
        m0 = fmaxf(m0, __shfl_xor_sync(0xffffffffu, m0, d));
        m1 = fmaxf(m1, __shfl_xor_sync(0xffffffffu, m1, d));
        m2 = fmaxf(m2, __shfl_xor_sync(0xffffffffu, m2, d));
        m3 = fmaxf(m3, __shfl_xor_sync(0xffffffffu, m3, d));
    }

    // pass 2: p = exp(e-m); denom += p; acc += p * h[src]
    float acc[RJ];
#pragma unroll
    for (int j = 0; j < RJ; j++) acc[j] = 0.f;
    float den0 = 0.f, den1 = 0.f, den2 = 0.f, den3 = 0.f;

    for (int i = beg; i < end; i += 32) {
        int cnt = min(32, end - i);
        int s_l = 0;
        float p0 = 0.f, p1 = 0.f, p2 = 0.f, p3 = 0.f;
        if (lane < cnt) {
            s_l = csr_src[i + lane];
            float4 es = ((const float4*)esrc)[s_l];
            float e0 = es.x + ed.x; e0 = e0 > 0.f ? e0 : SLOPE * e0;
            float e1 = es.y + ed.y; e1 = e1 > 0.f ? e1 : SLOPE * e1;
            float e2 = es.z + ed.z; e2 = e2 > 0.f ? e2 : SLOPE * e2;
            float e3 = es.w + ed.w; e3 = e3 > 0.f ? e3 : SLOPE * e3;
            p0 = __expf(e0 - m0); p1 = __expf(e1 - m1);
            p2 = __expf(e2 - m2); p3 = __expf(e3 - m3);
        }
        for (int k = 0; k < cnt; k++) {
            int   s  = __shfl_sync(0xffffffffu, s_l, k);
            float q0 = __shfl_sync(0xffffffffu, p0, k);
            float q1 = __shfl_sync(0xffffffffu, p1, k);
            float q2 = __shfl_sync(0xffffffffu, p2, k);
            float q3 = __shfl_sync(0xffffffffu, p3, k);
            den0 += q0; den1 += q1; den2 += q2; den3 += q3;
            float q[4] = {q0, q1, q2, q3};
            const float* row = hfeat + (size_t)s * HC + lane;
#pragma unroll
            for (int j = 0; j < RJ; j++) acc[j] += q[j >> HS] * row[32 * j];
        }
    }

    // epilogue in registers
    float den[4] = {den0, den1, den2, den3};
    float vals[RJ];
    float sum = 0.f;
#pragma unroll
    for (int j = 0; j < RJ; j++) {
        int f = lane + 32 * j;
        float v = acc[j] / den[j >> HS] + bias[f];
        if (DOELU) v = v > 0.f ? v : expm1f(v);
        vals[j] = v;
        sum += v;
    }
#pragma unroll
    for (int d = 16; d > 0; d >>= 1) sum += __shfl_xor_sync(0xffffffffu, sum, d);
    float mu = sum / (float)HC;
    float vs = 0.f;
#pragma unroll
    for (int j = 0; j < RJ; j++) {
        float dv = vals[j] - mu;
        vs += dv * dv;
    }
#pragma unroll
    for (int d = 16; d > 0; d >>= 1) vs += __shfl_xor_sync(0xffffffffu, vs, d);
    float rstd = rsqrtf(vs / (float)HC + LN_EPS);
#pragma unroll
    for (int j = 0; j < RJ; j++) {
        int f = lane + 32 * j;
        outp[(size_t)n * HC + f] = gam[f] * (vals[j] - mu) * rstd + bet[f];
    }
}

// ---------------- mean pool: block per graph, binary search (batch sorted) ---
__global__ void pool_kernel(const float* __restrict__ node_out, const int* __restrict__ batch,
                            float* __restrict__ graph_out, int Nn) {
    int g = blockIdx.x;
    int f = threadIdx.x;  // 128
    int lo = 0, hi = Nn;
    while (lo < hi) { int mid = (lo + hi) >> 1; if (batch[mid] < g) lo = mid + 1; else hi = mid; }
    int start = lo;
    lo = start; hi = Nn;
    while (lo < hi) { int mid = (lo + hi) >> 1; if (batch[mid] < g + 1) lo = mid + 1; else hi = mid; }
    int end = lo;
    float s = 0.f;
    for (int n = start; n < end; n++) s += node_out[(size_t)n * 128 + f];
    graph_out[g * 128 + f] = s / fmaxf((float)(end - start), 1.f);
}

// ---------------- launch -----------------------------------------------------
extern "C" void kernel_launch(void* const* d_in, const int* in_sizes, int n_in,
                              void* d_out, int out_size) {
    const float* x     = (const float*)d_in[0];
    const int*   ei    = (const int*)d_in[1];
    const int*   batch = (const int*)d_in[2];
    const float* W[3]    = {(const float*)d_in[3],  (const float*)d_in[9],  (const float*)d_in[15]};
    const float* asrc[3] = {(const float*)d_in[4],  (const float*)d_in[10], (const float*)d_in[16]};
    const float* adst[3] = {(const float*)d_in[5],  (const float*)d_in[11], (const float*)d_in[17]};
    const float* bia[3]  = {(const float*)d_in[6],  (const float*)d_in[12], (const float*)d_in[18]};
    const float* gam[3]  = {(const float*)d_in[7],  (const float*)d_in[13], (const float*)d_in[19]};
    const float* bet[3]  = {(const float*)d_in[8],  (const float*)d_in[14], (const float*)d_in[20]};

    int N = in_sizes[0] / 768;
    int E = in_sizes[1] / 2;
    int Etot = E + N;
    const int* srcA = ei;
    const int* dstA = ei + E;

    float* node_out  = (float*)d_out;
    float* graph_out = node_out + (size_t)N * 128;

    float *p_h, *p_in, *p_esrc, *p_edst;
    int *p_deg, *p_off, *p_cur, *p_csr;
    cudaGetSymbolAddress((void**)&p_h, g_h);
    cudaGetSymbolAddress((void**)&p_in, g_in);
    cudaGetSymbolAddress((void**)&p_esrc, g_esrc);
    cudaGetSymbolAddress((void**)&p_edst, g_edst);
    cudaGetSymbolAddress((void**)&p_deg, g_deg);
    cudaGetSymbolAddress((void**)&p_off, g_off);
    cudaGetSymbolAddress((void**)&p_cur, g_cur);
    cudaGetSymbolAddress((void**)&p_csr, g_csr);

    // ---- build dst-CSR once (shared across all 3 layers) ----
    init_deg_kernel<<<(N + 255) / 256, 256>>>(p_deg, p_cur, N);
    deg_hist_kernel<<<(E + 255) / 256, 256>>>(dstA, E, p_deg);
    scan_kernel<<<1, 1024>>>(p_deg, p_off, N);
    csr_scatter_kernel<<<(Etot + 255) / 256, 256>>>(srcA, dstA, E, Etot, p_off, p_cur, p_csr);

    int dins[3] = {768, 256, 256};
    int HCs[3]  = {256, 256, 128};
    const float* inputs[3] = {x, p_in, p_in};
    float* outs[3] = {p_in, p_in, node_out};

    for (int L = 0; L < 3; L++) {
        int K = dins[L], HC = HCs[L];

        dim3 ggrid(HC / 128, (N + 127) / 128);
        sgemm_kernel<<<ggrid, 256>>>(inputs[L], W[L], p_h, N, K, HC);

        int nwb = (N + 7) / 8;   // 8 warps / block
        if (HC == 256) {
            scores_warp_kernel<8, 1><<<nwb, 256>>>(p_h, asrc[L], adst[L], p_esrc, p_edst, N);
            if (L < 2)
                gat_agg_kernel<8, 1, 1><<<nwb, 256>>>(p_h, p_esrc, p_edst, p_off, p_csr,
                                                      bia[L], gam[L], bet[L], outs[L], N);
            else
                gat_agg_kernel<8, 1, 0><<<nwb, 256>>>(p_h, p_esrc, p_edst, p_off, p_csr,
                                                      bia[L], gam[L], bet[L], outs[L], N);
        } else {
            scores_warp_kernel<4, 0><<<nwb, 256>>>(p_h, asrc[L], adst[L], p_esrc, p_edst, N);
            gat_agg_kernel<4, 0, 0><<<nwb, 256>>>(p_h, p_esrc, p_edst, p_off, p_csr,
                                                  bia[L], gam[L], bet[L], outs[L], N);
        }
    }

    pool_kernel<<<GMAX, 128>>>(node_out, batch, graph_out, N);
}

// round 6
// speedup vs baseline: 1.8340x; 1.1212x over previous
#include <cuda_runtime.h>
#include <math.h>
#include <stdint.h>

#define NMAX 50000
#define EMAX 800000
#define ETOTMAX (EMAX + NMAX)
#define GMAX 64
#define LN_EPS 1e-5f
#define SLOPE 0.2f

// ---------------- scratch (static device globals; no runtime alloc) ----------
__device__ float g_h   [(size_t)NMAX * 256];   // GEMM output (pre-aggregation features)
__device__ float g_in  [(size_t)NMAX * 256];   // normalized features (input to next layer)
__device__ float g_esrc[NMAX * 4];
__device__ float g_edst[NMAX * 4];
__device__ int   g_deg [NMAX + 1];
__device__ int   g_off [NMAX + 1];
__device__ int   g_cur [NMAX];
__device__ int   g_csr [ETOTMAX];

// ---------------- CSR build --------------------------------------------------
__global__ void init_deg_kernel(int* __restrict__ deg, int* __restrict__ cur, int Nn) {
    int i = blockIdx.x * blockDim.x + threadIdx.x;
    if (i < Nn) { deg[i] = 1; cur[i] = 0; }   // deg starts at 1: self-loop
}

__global__ void deg_hist_kernel(const int* __restrict__ dst, int E_, int* __restrict__ deg) {
    int i = blockIdx.x * blockDim.x + threadIdx.x;
    if (i < E_) atomicAdd(&deg[dst[i]], 1);
}

// single-block exclusive scan over n ints: warp-scan + carry loop
__global__ void scan_kernel(const int* __restrict__ deg, int* __restrict__ off, int n) {
    __shared__ int warp_sums[32];
    __shared__ int s_carry;
    int tid = threadIdx.x;           // 1024 threads
    int lane = tid & 31, wid = tid >> 5;
    if (tid == 0) s_carry = 0;
    __syncthreads();
    for (int base = 0; base < n; base += 1024) {
        int idx = base + tid;
        int v = (idx < n) ? deg[idx] : 0;
        int incl = v;
#pragma unroll
        for (int d = 1; d < 32; d <<= 1) {
            int t = __shfl_up_sync(0xffffffffu, incl, d);
            if (lane >= d) incl += t;
        }
        if (lane == 31) warp_sums[wid] = incl;
        __syncthreads();
        if (wid == 0) {
            int ws = warp_sums[lane];
            int wincl = ws;
#pragma unroll
            for (int d = 1; d < 32; d <<= 1) {
                int t = __shfl_up_sync(0xffffffffu, wincl, d);
                if (lane >= d) wincl += t;
            }
            warp_sums[lane] = wincl - ws;   // exclusive prefix of warp sums
        }
        __syncthreads();
        int carry = s_carry;
        if (idx < n) off[idx] = carry + warp_sums[wid] + incl - v;
        __syncthreads();
        if (tid == 1023) s_carry = carry + warp_sums[31] + incl;
        __syncthreads();
    }
    if (tid == 0) off[n] = s_carry;
}

__global__ void csr_scatter_kernel(const int* __restrict__ src, const int* __restrict__ dst,
                                   int E_, int Etot,
                                   const int* __restrict__ off, int* __restrict__ cur,
                                   int* __restrict__ csr_src) {
    int i = blockIdx.x * blockDim.x + threadIdx.x;
    if (i >= Etot) return;
    int s, d;
    if (i < E_) { s = src[i]; d = dst[i]; } else { s = d = i - E_; }
    int pos = off[d] + atomicAdd(&cur[d], 1);
    csr_src[pos] = s;
}

// ---------------- TF32 tensor-core GEMM with hi/lo split (3xTF32) ------------
// C[M,N] = A[M,K] @ B[K,N], fp32 in/out, fp32-grade accuracy.
// Block tile 128x128, BK=8, double-buffered smem, 8 warps @ 32x64 warp tiles.
// smem k-layout interleaved: pos(k) = (k&3)*2 + (k>>2) so that k and k+4 are
// adjacent. Fragment loads are SCALAR LDS.32 (stride-9 rows are only 4B
// aligned; LDS.64 there traps with misaligned address).

#define MMA_TF32(d, a, b0, b1)                                              \
    asm volatile("mma.sync.aligned.m16n8k8.row.col.f32.tf32.tf32.f32 "      \
                 "{%0,%1,%2,%3}, {%4,%5,%6,%7}, {%8,%9}, {%0,%1,%2,%3};\n"  \
                 : "+f"(d[0]), "+f"(d[1]), "+f"(d[2]), "+f"(d[3])           \
                 : "r"(a[0]), "r"(a[1]), "r"(a[2]), "r"(a[3]),              \
                   "r"(b0), "r"(b1))

__global__ __launch_bounds__(256) void tf32_gemm_kernel(
        const float* __restrict__ A, const float* __restrict__ B,
        float* __restrict__ C, int M, int K, int N) {
    __shared__ float As_hi[2][128 * 9];
    __shared__ float As_lo[2][128 * 9];
    __shared__ float Bs_hi[2][128 * 9];
    __shared__ float Bs_lo[2][128 * 9];

    const int tid  = threadIdx.x;
    const int warp = tid >> 5, lane = tid & 31;
    const int g = lane >> 2, tg = lane & 3;
    const int wy = warp & 3;   // 4 warps along M
    const int wx = warp >> 2;  // 2 warps along N
    const int bm = blockIdx.y * 128, bn = blockIdx.x * 128;

    // loader indices
    const int ar  = tid >> 1;          // A row 0..127
    const int ac4 = (tid & 1) * 4;     // A col {0,4}
    const int bk  = tid >> 5;          // B k-row 0..7
    const int bn4 = lane * 4;          // B col 0..124
    const int bposk = ((bk & 3) << 1) | (bk >> 2);

    float acc[2][8][4];
#pragma unroll
    for (int mt = 0; mt < 2; mt++)
#pragma unroll
        for (int nt = 0; nt < 8; nt++)
#pragma unroll
            for (int c = 0; c < 4; c++) acc[mt][nt][c] = 0.f;

    const int T = K >> 3;
    const bool arow_ok = (bm + ar) < M;

    float4 av, bv;
    // prologue: load k-tile 0
    av = arow_ok ? *(const float4*)(A + (size_t)(bm + ar) * K + ac4)
                 : make_float4(0.f, 0.f, 0.f, 0.f);
    bv = *(const float4*)(B + (size_t)bk * N + bn + bn4);
    {
        const int buf = 0;
#pragma unroll
        for (int j = 0; j < 4; j++) {
            int kk = ac4 + j;
            int pos = ((kk & 3) << 1) | (kk >> 2);
            float v = (&av.x)[j];
            float hi = __uint_as_float(__float_as_uint(v) & 0xFFFFE000u);
            As_hi[buf][ar * 9 + pos] = hi;
            As_lo[buf][ar * 9 + pos] = v - hi;
            float w = (&bv.x)[j];
            float whi = __uint_as_float(__float_as_uint(w) & 0xFFFFE000u);
            Bs_hi[buf][(bn4 + j) * 9 + bposk] = whi;
            Bs_lo[buf][(bn4 + j) * 9 + bposk] = w - whi;
        }
    }
    __syncthreads();

    for (int t = 0; t < T; t++) {
        const int buf = t & 1;
        if (t + 1 < T) {
            int k0 = (t + 1) << 3;
            av = arow_ok ? *(const float4*)(A + (size_t)(bm + ar) * K + k0 + ac4)
                         : make_float4(0.f, 0.f, 0.f, 0.f);
            bv = *(const float4*)(B + (size_t)(k0 + bk) * N + bn + bn4);
        }

        // ---- compute on buf (scalar LDS: stride-9 rows are 4B-aligned only) ----
        uint32_t ah[2][4], al[2][4];
#pragma unroll
        for (int mt = 0; mt < 2; mt++) {
            int r0 = (wy * 32 + mt * 16 + g) * 9 + 2 * tg;
            int r1 = r0 + 8 * 9;
            ah[mt][0] = __float_as_uint(As_hi[buf][r0]);
            ah[mt][2] = __float_as_uint(As_hi[buf][r0 + 1]);
            ah[mt][1] = __float_as_uint(As_hi[buf][r1]);
            ah[mt][3] = __float_as_uint(As_hi[buf][r1 + 1]);
            al[mt][0] = __float_as_uint(As_lo[buf][r0]);
            al[mt][2] = __float_as_uint(As_lo[buf][r0 + 1]);
            al[mt][1] = __float_as_uint(As_lo[buf][r1]);
            al[mt][3] = __float_as_uint(As_lo[buf][r1 + 1]);
        }
#pragma unroll
        for (int nt = 0; nt < 8; nt++) {
            int ni = (wx * 64 + nt * 8 + g) * 9 + 2 * tg;
            uint32_t bh0 = __float_as_uint(Bs_hi[buf][ni]);
            uint32_t bh1 = __float_as_uint(Bs_hi[buf][ni + 1]);
            uint32_t bl0 = __float_as_uint(Bs_lo[buf][ni]);
            uint32_t bl1 = __float_as_uint(Bs_lo[buf][ni + 1]);
#pragma unroll
            for (int mt = 0; mt < 2; mt++) {
                MMA_TF32(acc[mt][nt], ah[mt], bh0, bh1);
                MMA_TF32(acc[mt][nt], ah[mt], bl0, bl1);
                MMA_TF32(acc[mt][nt], al[mt], bh0, bh1);
            }
        }

        // ---- store next tile into other buffer ----
        if (t + 1 < T) {
            const int nbuf = (t + 1) & 1;
#pragma unroll
            for (int j = 0; j < 4; j++) {
                int kk = ac4 + j;
                int pos = ((kk & 3) << 1) | (kk >> 2);
                float v = (&av.x)[j];
                float hi = __uint_as_float(__float_as_uint(v) & 0xFFFFE000u);
                As_hi[nbuf][ar * 9 + pos] = hi;
                As_lo[nbuf][ar * 9 + pos] = v - hi;
                float w = (&bv.x)[j];
                float whi = __uint_as_float(__float_as_uint(w) & 0xFFFFE000u);
                Bs_hi[nbuf][(bn4 + j) * 9 + bposk] = whi;
                Bs_lo[nbuf][(bn4 + j) * 9 + bposk] = w - whi;
            }
        }
        __syncthreads();
    }

    // epilogue: write C (col is even; rows 128-float aligned -> float2 OK)
#pragma unroll
    for (int mt = 0; mt < 2; mt++) {
        int gr0 = bm + wy * 32 + mt * 16 + g;
        int gr1 = gr0 + 8;
#pragma unroll
        for (int nt = 0; nt < 8; nt++) {
            int col = bn + wx * 64 + nt * 8 + 2 * tg;
            if (gr0 < M) {
                float2 v = make_float2(acc[mt][nt][0], acc[mt][nt][1]);
                *(float2*)(C + (size_t)gr0 * N + col) = v;
            }
            if (gr1 < M) {
                float2 v = make_float2(acc[mt][nt][2], acc[mt][nt][3]);
                *(float2*)(C + (size_t)gr1 * N + col) = v;
            }
        }
    }
}

// ---------------- attention scores: warp per node, coalesced -----------------
template<int RJ, int HS>
__global__ void scores_warp_kernel(const float* __restrict__ h,
                                   const float* __restrict__ asrc, const float* __restrict__ adst,
                                   float* __restrict__ esrc, float* __restrict__ edst, int Nn) {
    const int HC = RJ * 32;
    int warp = (blockIdx.x * blockDim.x + threadIdx.x) >> 5;
    int lane = threadIdx.x & 31;
    if (warp >= Nn) return;
    float ps[4] = {0.f, 0.f, 0.f, 0.f};
    float pd[4] = {0.f, 0.f, 0.f, 0.f};
#pragma unroll
    for (int j = 0; j < RJ; j++) {
        int f = lane + 32 * j;
        float v = h[(size_t)warp * HC + f];
        int hd = j >> HS;
        ps[hd] += v * asrc[f];
        pd[hd] += v * adst[f];
    }
#pragma unroll
    for (int hd = 0; hd < 4; hd++) {
#pragma unroll
        for (int d = 16; d > 0; d >>= 1) {
            ps[hd] += __shfl_xor_sync(0xffffffffu, ps[hd], d);
            pd[hd] += __shfl_xor_sync(0xffffffffu, pd[hd], d);
        }
    }
    if (lane < 4) {
        esrc[warp * 4 + lane] = ps[lane];
        edst[warp * 4 + lane] = pd[lane];
    }
}

// ---------------- fully fused aggregation: warp per dst node -----------------
template<int RJ, int HS, int DOELU>
__global__ void gat_agg_kernel(const float* __restrict__ hfeat,
                               const float* __restrict__ esrc, const float* __restrict__ edst,
                               const int* __restrict__ off, const int* __restrict__ csr_src,
                               const float* __restrict__ bias,
                               const float* __restrict__ gam, const float* __restrict__ bet,
                               float* __restrict__ outp, int Nn) {
    const int HC = RJ * 32;
    int n = (blockIdx.x * blockDim.x + threadIdx.x) >> 5;
    int lane = threadIdx.x & 31;
    if (n >= Nn) return;

    int beg = off[n], end = off[n + 1];
    float4 ed = ((const float4*)edst)[n];

    // pass 1: segment max per head
    float m0 = -INFINITY, m1 = -INFINITY, m2 = -INFINITY, m3 = -INFINITY;
    for (int i = beg + lane; i < end; i += 32) {
        int s = csr_src[i];
        float4 es = ((const float4*)esrc)[s];
        float e0 = es.x + ed.x; e0 = e0 > 0.f ? e0 : SLOPE * e0; m0 = fmaxf(m0, e0);
        float e1 = es.y + ed.y; e1 = e1 > 0.f ? e1 : SLOPE * e1; m1 = fmaxf(m1, e1);
        float e2 = es.z + ed.z; e2 = e2 > 0.f ? e2 : SLOPE * e2; m2 = fmaxf(m2, e2);
        float e3 = es.w + ed.w; e3 = e3 > 0.f ? e3 : SLOPE * e3; m3 = fmaxf(m3, e3);
    }
#pragma unroll
    for (int d = 16; d > 0; d >>= 1) {
        m0 = fmaxf(m0, __shfl_xor_sync(0xffffffffu, m0, d));
        m1 = fmaxf(m1, __shfl_xor_sync(0xffffffffu, m1, d));
        m2 = fmaxf(m2, __shfl_xor_sync(0xffffffffu, m2, d));
        m3 = fmaxf(m3, __shfl_xor_sync(0xffffffffu, m3, d));
    }

    // pass 2: p = exp(e-m); denom += p; acc += p * h[src]
    float acc[RJ];
#pragma unroll
    for (int j = 0; j < RJ; j++) acc[j] = 0.f;
    float den0 = 0.f, den1 = 0.f, den2 = 0.f, den3 = 0.f;

    for (int i = beg; i < end; i += 32) {
        int cnt = min(32, end - i);
        int s_l = 0;
        float p0 = 0.f, p1 = 0.f, p2 = 0.f, p3 = 0.f;
        if (lane < cnt) {
            s_l = csr_src[i + lane];
            float4 es = ((const float4*)esrc)[s_l];
            float e0 = es.x + ed.x; e0 = e0 > 0.f ? e0 : SLOPE * e0;
            float e1 = es.y + ed.y; e1 = e1 > 0.f ? e1 : SLOPE * e1;
            float e2 = es.z + ed.z; e2 = e2 > 0.f ? e2 : SLOPE * e2;
            float e3 = es.w + ed.w; e3 = e3 > 0.f ? e3 : SLOPE * e3;
            p0 = __expf(e0 - m0); p1 = __expf(e1 - m1);
            p2 = __expf(e2 - m2); p3 = __expf(e3 - m3);
        }
        for (int k = 0; k < cnt; k++) {
            int   s  = __shfl_sync(0xffffffffu, s_l, k);
            float q0 = __shfl_sync(0xffffffffu, p0, k);
            float q1 = __shfl_sync(0xffffffffu, p1, k);
            float q2 = __shfl_sync(0xffffffffu, p2, k);
            float q3 = __shfl_sync(0xffffffffu, p3, k);
            den0 += q0; den1 += q1; den2 += q2; den3 += q3;
            float q[4] = {q0, q1, q2, q3};
            const float* row = hfeat + (size_t)s * HC + lane;
#pragma unroll
            for (int j = 0; j < RJ; j++) acc[j] += q[j >> HS] * row[32 * j];
        }
    }

    // epilogue in registers
    float den[4] = {den0, den1, den2, den3};
    float vals[RJ];
    float sum = 0.f;
#pragma unroll
    for (int j = 0; j < RJ; j++) {
        int f = lane + 32 * j;
        float v = acc[j] / den[j >> HS] + bias[f];
        if (DOELU) v = v > 0.f ? v : expm1f(v);
        vals[j] = v;
        sum += v;
    }
#pragma unroll
    for (int d = 16; d > 0; d >>= 1) sum += __shfl_xor_sync(0xffffffffu, sum, d);
    float mu = sum / (float)HC;
    float vs = 0.f;
#pragma unroll
    for (int j = 0; j < RJ; j++) {
        float dv = vals[j] - mu;
        vs += dv * dv;
    }
#pragma unroll
    for (int d = 16; d > 0; d >>= 1) vs += __shfl_xor_sync(0xffffffffu, vs, d);
    float rstd = rsqrtf(vs / (float)HC + LN_EPS);
#pragma unroll
    for (int j = 0; j < RJ; j++) {
        int f = lane + 32 * j;
        outp[(size_t)n * HC + f] = gam[f] * (vals[j] - mu) * rstd + bet[f];
    }
}

// ---------------- mean pool: block per graph, binary search (batch sorted) ---
__global__ void pool_kernel(const float* __restrict__ node_out, const int* __restrict__ batch,
                            float* __restrict__ graph_out, int Nn) {
    int g = blockIdx.x;
    int f = threadIdx.x;  // 128
    int lo = 0, hi = Nn;
    while (lo < hi) { int mid = (lo + hi) >> 1; if (batch[mid] < g) lo = mid + 1; else hi = mid; }
    int start = lo;
    lo = start; hi = Nn;
    while (lo < hi) { int mid = (lo + hi) >> 1; if (batch[mid] < g + 1) lo = mid + 1; else hi = mid; }
    int end = lo;
    float s = 0.f;
    for (int n = start; n < end; n++) s += node_out[(size_t)n * 128 + f];
    graph_out[g * 128 + f] = s / fmaxf((float)(end - start), 1.f);
}

// ---------------- launch -----------------------------------------------------
extern "C" void kernel_launch(void* const* d_in, const int* in_sizes, int n_in,
                              void* d_out, int out_size) {
    const float* x     = (const float*)d_in[0];
    const int*   ei    = (const int*)d_in[1];
    const int*   batch = (const int*)d_in[2];
    const float* W[3]    = {(const float*)d_in[3],  (const float*)d_in[9],  (const float*)d_in[15]};
    const float* asrc[3] = {(const float*)d_in[4],  (const float*)d_in[10], (const float*)d_in[16]};
    const float* adst[3] = {(const float*)d_in[5],  (const float*)d_in[11], (const float*)d_in[17]};
    const float* bia[3]  = {(const float*)d_in[6],  (const float*)d_in[12], (const float*)d_in[18]};
    const float* gam[3]  = {(const float*)d_in[7],  (const float*)d_in[13], (const float*)d_in[19]};
    const float* bet[3]  = {(const float*)d_in[8],  (const float*)d_in[14], (const float*)d_in[20]};

    int N = in_sizes[0] / 768;
    int E = in_sizes[1] / 2;
    int Etot = E + N;
    const int* srcA = ei;
    const int* dstA = ei + E;

    float* node_out  = (float*)d_out;
    float* graph_out = node_out + (size_t)N * 128;

    float *p_h, *p_in, *p_esrc, *p_edst;
    int *p_deg, *p_off, *p_cur, *p_csr;
    cudaGetSymbolAddress((void**)&p_h, g_h);
    cudaGetSymbolAddress((void**)&p_in, g_in);
    cudaGetSymbolAddress((void**)&p_esrc, g_esrc);
    cudaGetSymbolAddress((void**)&p_edst, g_edst);
    cudaGetSymbolAddress((void**)&p_deg, g_deg);
    cudaGetSymbolAddress((void**)&p_off, g_off);
    cudaGetSymbolAddress((void**)&p_cur, g_cur);
    cudaGetSymbolAddress((void**)&p_csr, g_csr);

    // ---- build dst-CSR once (shared across all 3 layers) ----
    init_deg_kernel<<<(N + 255) / 256, 256>>>(p_deg, p_cur, N);
    deg_hist_kernel<<<(E + 255) / 256, 256>>>(dstA, E, p_deg);
    scan_kernel<<<1, 1024>>>(p_deg, p_off, N);
    csr_scatter_kernel<<<(Etot + 255) / 256, 256>>>(srcA, dstA, E, Etot, p_off, p_cur, p_csr);

    int dins[3] = {768, 256, 256};
    int HCs[3]  = {256, 256, 128};
    const float* inputs[3] = {x, p_in, p_in};
    float* outs[3] = {p_in, p_in, node_out};

    for (int L = 0; L < 3; L++) {
        int K = dins[L], HC = HCs[L];

        dim3 ggrid(HC / 128, (N + 127) / 128);
        tf32_gemm_kernel<<<ggrid, 256>>>(inputs[L], W[L], p_h, N, K, HC);

        int nwb = (N + 7) / 8;   // 8 warps / block
        if (HC == 256) {
            scores_warp_kernel<8, 1><<<nwb, 256>>>(p_h, asrc[L], adst[L], p_esrc, p_edst, N);
            if (L < 2)
                gat_agg_kernel<8, 1, 1><<<nwb, 256>>>(p_h, p_esrc, p_edst, p_off, p_csr,
                                                      bia[L], gam[L], bet[L], outs[L], N);
            else
                gat_agg_kernel<8, 1, 0><<<nwb, 256>>>(p_h, p_esrc, p_edst, p_off, p_csr,
                                                      bia[L], gam[L], bet[L], outs[L], N);
        } else {
            scores_warp_kernel<4, 0><<<nwb, 256>>>(p_h, asrc[L], adst[L], p_esrc, p_edst, N);
            gat_agg_kernel<4, 0, 0><<<nwb, 256>>>(p_h, p_esrc, p_edst, p_off, p_csr,
                                                  bia[L], gam[L], bet[L], outs[L], N);
        }
    }

    pool_kernel<<<GMAX, 128>>>(node_out, batch, graph_out, N);
}

// round 7
// speedup vs baseline: 2.3522x; 1.2826x over previous
#include <cuda_runtime.h>
#include <cuda_bf16.h>
#include <math.h>
#include <stdint.h>

#define NMAX 50000
#define EMAX 800000
#define ETOTMAX (EMAX + NMAX)
#define GMAX 64
#define LN_EPS 1e-5f
#define SLOPE 0.2f

// ---------------- scratch (static device globals; no runtime alloc) ----------
__device__ float g_h   [(size_t)NMAX * 256];   // GEMM output (pre-aggregation features)
__device__ float g_in  [(size_t)NMAX * 256];   // normalized features (input to next layer)
__device__ float g_esrc[NMAX * 4];
__device__ float g_edst[NMAX * 4];
__device__ int   g_deg [NMAX + 1];
__device__ int   g_off [NMAX + 1];
__device__ int   g_cur [NMAX];
__device__ int   g_csr [ETOTMAX];

// ---------------- CSR build --------------------------------------------------
__global__ void init_deg_kernel(int* __restrict__ deg, int* __restrict__ cur, int Nn) {
    int i = blockIdx.x * blockDim.x + threadIdx.x;
    if (i < Nn) { deg[i] = 1; cur[i] = 0; }   // deg starts at 1: self-loop
}

__global__ void deg_hist_kernel(const int* __restrict__ dst, int E_, int* __restrict__ deg) {
    int i = blockIdx.x * blockDim.x + threadIdx.x;
    if (i < E_) atomicAdd(&deg[dst[i]], 1);
}

// single-block exclusive scan over n ints: warp-scan + carry loop
__global__ void scan_kernel(const int* __restrict__ deg, int* __restrict__ off, int n) {
    __shared__ int warp_sums[32];
    __shared__ int s_carry;
    int tid = threadIdx.x;           // 1024 threads
    int lane = tid & 31, wid = tid >> 5;
    if (tid == 0) s_carry = 0;
    __syncthreads();
    for (int base = 0; base < n; base += 1024) {
        int idx = base + tid;
        int v = (idx < n) ? deg[idx] : 0;
        int incl = v;
#pragma unroll
        for (int d = 1; d < 32; d <<= 1) {
            int t = __shfl_up_sync(0xffffffffu, incl, d);
            if (lane >= d) incl += t;
        }
        if (lane == 31) warp_sums[wid] = incl;
        __syncthreads();
        if (wid == 0) {
            int ws = warp_sums[lane];
            int wincl = ws;
#pragma unroll
            for (int d = 1; d < 32; d <<= 1) {
                int t = __shfl_up_sync(0xffffffffu, wincl, d);
                if (lane >= d) wincl += t;
            }
            warp_sums[lane] = wincl - ws;   // exclusive prefix of warp sums
        }
        __syncthreads();
        int carry = s_carry;
        if (idx < n) off[idx] = carry + warp_sums[wid] + incl - v;
        __syncthreads();
        if (tid == 1023) s_carry = carry + warp_sums[31] + incl;
        __syncthreads();
    }
    if (tid == 0) off[n] = s_carry;
}

__global__ void csr_scatter_kernel(const int* __restrict__ src, const int* __restrict__ dst,
                                   int E_, int Etot,
                                   const int* __restrict__ off, int* __restrict__ cur,
                                   int* __restrict__ csr_src) {
    int i = blockIdx.x * blockDim.x + threadIdx.x;
    if (i >= Etot) return;
    int s, d;
    if (i < E_) { s = src[i]; d = dst[i]; } else { s = d = i - E_; }
    int pos = off[d] + atomicAdd(&cur[d], 1);
    csr_src[pos] = s;
}

// ---------------- bf16 tensor-core GEMM with hi/lo split (3xBF16) ------------
// C[M,N] = A[M,K] @ B[K,N], fp32 in/out, ~1e-5 accuracy.
// v = hi + lo (both bf16); C = Ahi*Bhi + Ahi*Blo + Alo*Bhi (drop lo*lo ~2^-16).
// Block tile 128x128, BK=16, double-buffered smem, 8 warps @ 32x64 warp tiles.
// smem rows: 16 bf16 per k-tile row, stride 18 bf16 (36B). Fragment regs are
// k-pairs (2tg,2tg+1)/(+8): 4B-aligned single LDS.32 each.

#define MMA_BF16(d, a, b0, b1)                                               \
    asm volatile("mma.sync.aligned.m16n8k16.row.col.f32.bf16.bf16.f32 "      \
                 "{%0,%1,%2,%3}, {%4,%5,%6,%7}, {%8,%9}, {%0,%1,%2,%3};\n"   \
                 : "+f"(d[0]), "+f"(d[1]), "+f"(d[2]), "+f"(d[3])            \
                 : "r"(a[0]), "r"(a[1]), "r"(a[2]), "r"(a[3]),               \
                   "r"(b0), "r"(b1))

__device__ __forceinline__ void split_pack(float v0, float v1, uint32_t& hi, uint32_t& lo) {
    __nv_bfloat16 h0 = __float2bfloat16_rn(v0);
    __nv_bfloat16 h1 = __float2bfloat16_rn(v1);
    __nv_bfloat16 l0 = __float2bfloat16_rn(v0 - __bfloat162float(h0));
    __nv_bfloat16 l1 = __float2bfloat16_rn(v1 - __bfloat162float(h1));
    hi = (uint32_t)__bfloat16_as_ushort(h0) | ((uint32_t)__bfloat16_as_ushort(h1) << 16);
    lo = (uint32_t)__bfloat16_as_ushort(l0) | ((uint32_t)__bfloat16_as_ushort(l1) << 16);
}

#define SROW 18   // bf16 units per smem row (16 data + 2 pad)

__global__ __launch_bounds__(256) void bf16_gemm_kernel(
        const float* __restrict__ A, const float* __restrict__ B,
        float* __restrict__ C, int M, int K, int N) {
    // uint32 views: each word = bf16x2 (consecutive k). Row r word base = r*9.
    __shared__ uint32_t As_hi[2][128 * 9];
    __shared__ uint32_t As_lo[2][128 * 9];
    __shared__ uint32_t Bs_hi[2][128 * 9];
    __shared__ uint32_t Bs_lo[2][128 * 9];

    const int tid  = threadIdx.x;
    const int warp = tid >> 5, lane = tid & 31;
    const int g = lane >> 2, tg = lane & 3;
    const int wy = warp & 3;   // 4 warps along M
    const int wx = warp >> 2;  // 2 warps along N
    const int bm = blockIdx.y * 128, bn = blockIdx.x * 128;

    // A loader: thread -> row ar (0..127), cols ac..ac+7 (ac in {0,8})
    const int ar = tid >> 1;
    const int ac = (tid & 1) * 8;
    // B loader: warp kp (k-pair base 2*warp), lanes cover 4 consecutive n each
    const int kp = warp;            // 0..7 -> k rows 2kp, 2kp+1
    const int n0 = lane * 4;        // 0..124

    float acc[2][8][4];
#pragma unroll
    for (int mt = 0; mt < 2; mt++)
#pragma unroll
        for (int nt = 0; nt < 8; nt++)
#pragma unroll
            for (int c = 0; c < 4; c++) acc[mt][nt][c] = 0.f;

    const int T = K >> 4;
    const bool arow_ok = (bm + ar) < M;

    float4 a0v, a1v, b0v, b1v;
    // prologue: load k-tile 0
    if (arow_ok) {
        a0v = *(const float4*)(A + (size_t)(bm + ar) * K + ac);
        a1v = *(const float4*)(A + (size_t)(bm + ar) * K + ac + 4);
    } else {
        a0v = a1v = make_float4(0.f, 0.f, 0.f, 0.f);
    }
    b0v = *(const float4*)(B + (size_t)(2 * kp) * N + bn + n0);
    b1v = *(const float4*)(B + (size_t)(2 * kp + 1) * N + bn + n0);
    {
        const int buf = 0;
        const float* a0p = &a0v.x;
        const float* a1p = &a1v.x;
#pragma unroll
        for (int j = 0; j < 2; j++) {
            uint32_t h, l;
            split_pack(a0p[2 * j], a0p[2 * j + 1], h, l);
            As_hi[buf][ar * 9 + (ac >> 1) + j] = h;
            As_lo[buf][ar * 9 + (ac >> 1) + j] = l;
            split_pack(a1p[2 * j], a1p[2 * j + 1], h, l);
            As_hi[buf][ar * 9 + (ac >> 1) + 2 + j] = h;
            As_lo[buf][ar * 9 + (ac >> 1) + 2 + j] = l;
        }
        const float* b0p = &b0v.x;
        const float* b1p = &b1v.x;
#pragma unroll
        for (int j = 0; j < 4; j++) {
            uint32_t h, l;
            split_pack(b0p[j], b1p[j], h, l);   // (k=2kp, k=2kp+1) for col n0+j
            Bs_hi[buf][(n0 + j) * 9 + kp] = h;
            Bs_lo[buf][(n0 + j) * 9 + kp] = l;
        }
    }
    __syncthreads();

    for (int t = 0; t < T; t++) {
        const int buf = t & 1;
        if (t + 1 < T) {
            int k0 = (t + 1) << 4;
            if (arow_ok) {
                a0v = *(const float4*)(A + (size_t)(bm + ar) * K + k0 + ac);
                a1v = *(const float4*)(A + (size_t)(bm + ar) * K + k0 + ac + 4);
            }
            b0v = *(const float4*)(B + (size_t)(k0 + 2 * kp) * N + bn + n0);
            b1v = *(const float4*)(B + (size_t)(k0 + 2 * kp + 1) * N + bn + n0);
        }

        // ---- compute on buf ----
        uint32_t ah[2][4], al[2][4];
#pragma unroll
        for (int mt = 0; mt < 2; mt++) {
            int r0 = (wy * 32 + mt * 16 + g) * 9 + tg;   // word index: k-pair tg
            int r1 = r0 + 8 * 9;
            ah[mt][0] = As_hi[buf][r0];
            ah[mt][1] = As_hi[buf][r1];
            ah[mt][2] = As_hi[buf][r0 + 4];
            ah[mt][3] = As_hi[buf][r1 + 4];
            al[mt][0] = As_lo[buf][r0];
            al[mt][1] = As_lo[buf][r1];
            al[mt][2] = As_lo[buf][r0 + 4];
            al[mt][3] = As_lo[buf][r1 + 4];
        }
#pragma unroll
        for (int nt = 0; nt < 8; nt++) {
            int ni = (wx * 64 + nt * 8 + g) * 9 + tg;
            uint32_t bh0 = Bs_hi[buf][ni];
            uint32_t bh1 = Bs_hi[buf][ni + 4];
            uint32_t bl0 = Bs_lo[buf][ni];
            uint32_t bl1 = Bs_lo[buf][ni + 4];
#pragma unroll
            for (int mt = 0; mt < 2; mt++) {
                MMA_BF16(acc[mt][nt], ah[mt], bh0, bh1);
                MMA_BF16(acc[mt][nt], ah[mt], bl0, bl1);
                MMA_BF16(acc[mt][nt], al[mt], bh0, bh1);
            }
        }

        // ---- store next tile into other buffer ----
        if (t + 1 < T) {
            const int nbuf = (t + 1) & 1;
            const float* a0p = &a0v.x;
            const float* a1p = &a1v.x;
#pragma unroll
            for (int j = 0; j < 2; j++) {
                uint32_t h, l;
                split_pack(a0p[2 * j], a0p[2 * j + 1], h, l);
                As_hi[nbuf][ar * 9 + (ac >> 1) + j] = h;
                As_lo[nbuf][ar * 9 + (ac >> 1) + j] = l;
                split_pack(a1p[2 * j], a1p[2 * j + 1], h, l);
                As_hi[nbuf][ar * 9 + (ac >> 1) + 2 + j] = h;
                As_lo[nbuf][ar * 9 + (ac >> 1) + 2 + j] = l;
            }
            const float* b0p = &b0v.x;
            const float* b1p = &b1v.x;
#pragma unroll
            for (int j = 0; j < 4; j++) {
                uint32_t h, l;
                split_pack(b0p[j], b1p[j], h, l);
                Bs_hi[nbuf][(n0 + j) * 9 + kp] = h;
                Bs_lo[nbuf][(n0 + j) * 9 + kp] = l;
            }
        }
        __syncthreads();
    }

    // epilogue: write C (col even, rows aligned -> float2 OK)
#pragma unroll
    for (int mt = 0; mt < 2; mt++) {
        int gr0 = bm + wy * 32 + mt * 16 + g;
        int gr1 = gr0 + 8;
#pragma unroll
        for (int nt = 0; nt < 8; nt++) {
            int col = bn + wx * 64 + nt * 8 + 2 * tg;
            if (gr0 < M) {
                float2 v = make_float2(acc[mt][nt][0], acc[mt][nt][1]);
                *(float2*)(C + (size_t)gr0 * N + col) = v;
            }
            if (gr1 < M) {
                float2 v = make_float2(acc[mt][nt][2], acc[mt][nt][3]);
                *(float2*)(C + (size_t)gr1 * N + col) = v;
            }
        }
    }
}

// ---------------- attention scores: warp per node, coalesced -----------------
template<int RJ, int HS>
__global__ void scores_warp_kernel(const float* __restrict__ h,
                                   const float* __restrict__ asrc, const float* __restrict__ adst,
                                   float* __restrict__ esrc, float* __restrict__ edst, int Nn) {
    const int HC = RJ * 32;
    int warp = (blockIdx.x * blockDim.x + threadIdx.x) >> 5;
    int lane = threadIdx.x & 31;
    if (warp >= Nn) return;
    float ps[4] = {0.f, 0.f, 0.f, 0.f};
    float pd[4] = {0.f, 0.f, 0.f, 0.f};
#pragma unroll
    for (int j = 0; j < RJ; j++) {
        int f = lane + 32 * j;
        float v = h[(size_t)warp * HC + f];
        int hd = j >> HS;
        ps[hd] += v * asrc[f];
        pd[hd] += v * adst[f];
    }
#pragma unroll
    for (int hd = 0; hd < 4; hd++) {
#pragma unroll
        for (int d = 16; d > 0; d >>= 1) {
            ps[hd] += __shfl_xor_sync(0xffffffffu, ps[hd], d);
            pd[hd] += __shfl_xor_sync(0xffffffffu, pd[hd], d);
        }
    }
    if (lane < 4) {
        esrc[warp * 4 + lane] = ps[lane];
        edst[warp * 4 + lane] = pd[lane];
    }
}

// ---------------- fully fused aggregation: warp per dst node -----------------
template<int RJ, int HS, int DOELU>
__global__ void gat_agg_kernel(const float* __restrict__ hfeat,
                               const float* __restrict__ esrc, const float* __restrict__ edst,
                               const int* __restrict__ off, const int* __restrict__ csr_src,
                               const float* __restrict__ bias,
                               const float* __restrict__ gam, const float* __restrict__ bet,
                               float* __restrict__ outp, int Nn) {
    const int HC = RJ * 32;
    int n = (blockIdx.x * blockDim.x + threadIdx.x) >> 5;
    int lane = threadIdx.x & 31;
    if (n >= Nn) return;

    int beg = off[n], end = off[n + 1];
    float4 ed = ((const float4*)edst)[n];

    // pass 1: segment max per head
    float m0 = -INFINITY, m1 = -INFINITY, m2 = -INFINITY, m3 = -INFINITY;
    for (int i = beg + lane; i < end; i += 32) {
        int s = csr_src[i];
        float4 es = ((const float4*)esrc)[s];
        float e0 = es.x + ed.x; e0 = e0 > 0.f ? e0 : SLOPE * e0; m0 = fmaxf(m0, e0);
        float e1 = es.y + ed.y; e1 = e1 > 0.f ? e1 : SLOPE * e1; m1 = fmaxf(m1, e1);
        float e2 = es.z + ed.z; e2 = e2 > 0.f ? e2 : SLOPE * e2; m2 = fmaxf(m2, e2);
        float e3 = es.w + ed.w; e3 = e3 > 0.f ? e3 : SLOPE * e3; m3 = fmaxf(m3, e3);
    }
#pragma unroll
    for (int d = 16; d > 0; d >>= 1) {
        m0 = fmaxf(m0, __shfl_xor_sync(0xffffffffu, m0, d));
        m1 = fmaxf(m1, __shfl_xor_sync(0xffffffffu, m1, d));
        m2 = fmaxf(m2, __shfl_xor_sync(0xffffffffu, m2, d));
        m3 = fmaxf(m3, __shfl_xor_sync(0xffffffffu, m3, d));
    }

    // pass 2: p = exp(e-m); denom += p; acc += p * h[src]
    float acc[RJ];
#pragma unroll
    for (int j = 0; j < RJ; j++) acc[j] = 0.f;
    float den0 = 0.f, den1 = 0.f, den2 = 0.f, den3 = 0.f;

    for (int i = beg; i < end; i += 32) {
        int cnt = min(32, end - i);
        int s_l = 0;
        float p0 = 0.f, p1 = 0.f, p2 = 0.f, p3 = 0.f;
        if (lane < cnt) {
            s_l = csr_src[i + lane];
            float4 es = ((const float4*)esrc)[s_l];
            float e0 = es.x + ed.x; e0 = e0 > 0.f ? e0 : SLOPE * e0;
            float e1 = es.y + ed.y; e1 = e1 > 0.f ? e1 : SLOPE * e1;
            float e2 = es.z + ed.z; e2 = e2 > 0.f ? e2 : SLOPE * e2;
            float e3 = es.w + ed.w; e3 = e3 > 0.f ? e3 : SLOPE * e3;
            p0 = __expf(e0 - m0); p1 = __expf(e1 - m1);
            p2 = __expf(e2 - m2); p3 = __expf(e3 - m3);
        }
        for (int k = 0; k < cnt; k++) {
            int   s  = __shfl_sync(0xffffffffu, s_l, k);
            float q0 = __shfl_sync(0xffffffffu, p0, k);
            float q1 = __shfl_sync(0xffffffffu, p1, k);
            float q2 = __shfl_sync(0xffffffffu, p2, k);
            float q3 = __shfl_sync(0xffffffffu, p3, k);
            den0 += q0; den1 += q1; den2 += q2; den3 += q3;
            float q[4] = {q0, q1, q2, q3};
            const float* row = hfeat + (size_t)s * HC + lane;
#pragma unroll
            for (int j = 0; j < RJ; j++) acc[j] += q[j >> HS] * row[32 * j];
        }
    }

    // epilogue in registers
    float den[4] = {den0, den1, den2, den3};
    float vals[RJ];
    float sum = 0.f;
#pragma unroll
    for (int j = 0; j < RJ; j++) {
        int f = lane + 32 * j;
        float v = acc[j] / den[j >> HS] + bias[f];
        if (DOELU) v = v > 0.f ? v : expm1f(v);
        vals[j] = v;
        sum += v;
    }
#pragma unroll
    for (int d = 16; d > 0; d >>= 1) sum += __shfl_xor_sync(0xffffffffu, sum, d);
    float mu = sum / (float)HC;
    float vs = 0.f;
#pragma unroll
    for (int j = 0; j < RJ; j++) {
        float dv = vals[j] - mu;
        vs += dv * dv;
    }
#pragma unroll
    for (int d = 16; d > 0; d >>= 1) vs += __shfl_xor_sync(0xffffffffu, vs, d);
    float rstd = rsqrtf(vs / (float)HC + LN_EPS);
#pragma unroll
    for (int j = 0; j < RJ; j++) {
        int f = lane + 32 * j;
        outp[(size_t)n * HC + f] = gam[f] * (vals[j] - mu) * rstd + bet[f];
    }
}

// ---------------- mean pool: block per graph, binary search (batch sorted) ---
__global__ void pool_kernel(const float* __restrict__ node_out, const int* __restrict__ batch,
                            float* __restrict__ graph_out, int Nn) {
    int g = blockIdx.x;
    int f = threadIdx.x;  // 128
    int lo = 0, hi = Nn;
    while (lo < hi) { int mid = (lo + hi) >> 1; if (batch[mid] < g) lo = mid + 1; else hi = mid; }
    int start = lo;
    lo = start; hi = Nn;
    while (lo < hi) { int mid = (lo + hi) >> 1; if (batch[mid] < g + 1) lo = mid + 1; else hi = mid; }
    int end = lo;
    float s = 0.f;
    for (int n = start; n < end; n++) s += node_out[(size_t)n * 128 + f];
    graph_out[g * 128 + f] = s / fmaxf((float)(end - start), 1.f);
}

// ---------------- launch -----------------------------------------------------
extern "C" void kernel_launch(void* const* d_in, const int* in_sizes, int n_in,
                              void* d_out, int out_size) {
    const float* x     = (const float*)d_in[0];
    const int*   ei    = (const int*)d_in[1];
    const int*   batch = (const int*)d_in[2];
    const float* W[3]    = {(const float*)d_in[3],  (const float*)d_in[9],  (const float*)d_in[15]};
    const float* asrc[3] = {(const float*)d_in[4],  (const float*)d_in[10], (const float*)d_in[16]};
    const float* adst[3] = {(const float*)d_in[5],  (const float*)d_in[11], (const float*)d_in[17]};
    const float* bia[3]  = {(const float*)d_in[6],  (const float*)d_in[12], (const float*)d_in[18]};
    const float* gam[3]  = {(const float*)d_in[7],  (const float*)d_in[13], (const float*)d_in[19]};
    const float* bet[3]  = {(const float*)d_in[8],  (const float*)d_in[14], (const float*)d_in[20]};

    int N = in_sizes[0] / 768;
    int E = in_sizes[1] / 2;
    int Etot = E + N;
    const int* srcA = ei;
    const int* dstA = ei + E;

    float* node_out  = (float*)d_out;
    float* graph_out = node_out + (size_t)N * 128;

    float *p_h, *p_in, *p_esrc, *p_edst;
    int *p_deg, *p_off, *p_cur, *p_csr;
    cudaGetSymbolAddress((void**)&p_h, g_h);
    cudaGetSymbolAddress((void**)&p_in, g_in);
    cudaGetSymbolAddress((void**)&p_esrc, g_esrc);
    cudaGetSymbolAddress((void**)&p_edst, g_edst);
    cudaGetSymbolAddress((void**)&p_deg, g_deg);
    cudaGetSymbolAddress((void**)&p_off, g_off);
    cudaGetSymbolAddress((void**)&p_cur, g_cur);
    cudaGetSymbolAddress((void**)&p_csr, g_csr);

    // ---- build dst-CSR once (shared across all 3 layers) ----
    init_deg_kernel<<<(N + 255) / 256, 256>>>(p_deg, p_cur, N);
    deg_hist_kernel<<<(E + 255) / 256, 256>>>(dstA, E, p_deg);
    scan_kernel<<<1, 1024>>>(p_deg, p_off, N);
    csr_scatter_kernel<<<(Etot + 255) / 256, 256>>>(srcA, dstA, E, Etot, p_off, p_cur, p_csr);

    int dins[3] = {768, 256, 256};
    int HCs[3]  = {256, 256, 128};
    const float* inputs[3] = {x, p_in, p_in};
    float* outs[3] = {p_in, p_in, node_out};

    for (int L = 0; L < 3; L++) {
        int K = dins[L], HC = HCs[L];

        dim3 ggrid(HC / 128, (N + 127) / 128);
        bf16_gemm_kernel<<<ggrid, 256>>>(inputs[L], W[L], p_h, N, K, HC);

        int nwb = (N + 7) / 8;   // 8 warps / block
        if (HC == 256) {
            scores_warp_kernel<8, 1><<<nwb, 256>>>(p_h, asrc[L], adst[L], p_esrc, p_edst, N);
            if (L < 2)
                gat_agg_kernel<8, 1, 1><<<nwb, 256>>>(p_h, p_esrc, p_edst, p_off, p_csr,
                                                      bia[L], gam[L], bet[L], outs[L], N);
            else
                gat_agg_kernel<8, 1, 0><<<nwb, 256>>>(p_h, p_esrc, p_edst, p_off, p_csr,
                                                      bia[L], gam[L], bet[L], outs[L], N);
        } else {
            scores_warp_kernel<4, 0><<<nwb, 256>>>(p_h, asrc[L], adst[L], p_esrc, p_edst, N);
            gat_agg_kernel<4, 0, 0><<<nwb, 256>>>(p_h, p_esrc, p_edst, p_off, p_csr,
                                                  bia[L], gam[L], bet[L], outs[L], N);
        }
    }

    pool_kernel<<<GMAX, 128>>>(node_out, batch, graph_out, N);
}

// round 8
// speedup vs baseline: 2.3624x; 1.0044x over previous
#include <cuda_runtime.h>
#include <cuda_bf16.h>
#include <cuda_fp16.h>
#include <math.h>
#include <stdint.h>

#define NMAX 50000
#define EMAX 800000
#define ETOTMAX (EMAX + NMAX)
#define GMAX 64
#define LN_EPS 1e-5f
#define SLOPE 0.2f

// ---------------- scratch (static device globals; no runtime alloc) ----------
__device__ __half2 g_h16[(size_t)NMAX * 128];  // GEMM output, fp16 (256 halves/node)
__device__ float g_in  [(size_t)NMAX * 256];   // normalized features (input to next layer)
__device__ float g_esrc[NMAX * 4];
__device__ float g_edst[NMAX * 4];
__device__ int   g_deg [NMAX + 1];
__device__ int   g_off [NMAX + 1];
__device__ int   g_cur [NMAX];
__device__ int   g_csr [ETOTMAX];

// ---------------- CSR build --------------------------------------------------
__global__ void init_deg_kernel(int* __restrict__ deg, int* __restrict__ cur, int Nn) {
    int i = blockIdx.x * blockDim.x + threadIdx.x;
    if (i < Nn) { deg[i] = 1; cur[i] = 0; }   // deg starts at 1: self-loop
}

__global__ void deg_hist_kernel(const int* __restrict__ dst, int E_, int* __restrict__ deg) {
    int i = blockIdx.x * blockDim.x + threadIdx.x;
    if (i < E_) atomicAdd(&deg[dst[i]], 1);
}

// single-block exclusive scan over n ints: warp-scan + carry loop
__global__ void scan_kernel(const int* __restrict__ deg, int* __restrict__ off, int n) {
    __shared__ int warp_sums[32];
    __shared__ int s_carry;
    int tid = threadIdx.x;           // 1024 threads
    int lane = tid & 31, wid = tid >> 5;
    if (tid == 0) s_carry = 0;
    __syncthreads();
    for (int base = 0; base < n; base += 1024) {
        int idx = base + tid;
        int v = (idx < n) ? deg[idx] : 0;
        int incl = v;
#pragma unroll
        for (int d = 1; d < 32; d <<= 1) {
            int t = __shfl_up_sync(0xffffffffu, incl, d);
            if (lane >= d) incl += t;
        }
        if (lane == 31) warp_sums[wid] = incl;
        __syncthreads();
        if (wid == 0) {
            int ws = warp_sums[lane];
            int wincl = ws;
#pragma unroll
            for (int d = 1; d < 32; d <<= 1) {
                int t = __shfl_up_sync(0xffffffffu, wincl, d);
                if (lane >= d) wincl += t;
            }
            warp_sums[lane] = wincl - ws;   // exclusive prefix of warp sums
        }
        __syncthreads();
        int carry = s_carry;
        if (idx < n) off[idx] = carry + warp_sums[wid] + incl - v;
        __syncthreads();
        if (tid == 1023) s_carry = carry + warp_sums[31] + incl;
        __syncthreads();
    }
    if (tid == 0) off[n] = s_carry;
}

__global__ void csr_scatter_kernel(const int* __restrict__ src, const int* __restrict__ dst,
                                   int E_, int Etot,
                                   const int* __restrict__ off, int* __restrict__ cur,
                                   int* __restrict__ csr_src) {
    int i = blockIdx.x * blockDim.x + threadIdx.x;
    if (i >= Etot) return;
    int s, d;
    if (i < E_) { s = src[i]; d = dst[i]; } else { s = d = i - E_; }
    int pos = off[d] + atomicAdd(&cur[d], 1);
    csr_src[pos] = s;
}

// ---------------- bf16 tensor-core GEMM with hi/lo split (3xBF16) ------------
// C16[M,N] (fp16) = A[M,K] @ B[K,N], fp32 inputs, ~1e-5 GEMM accuracy then
// fp16 store quantization. Block tile 128x128, BK=16, double-buffered smem,
// 8 warps @ 32x64 warp tiles.

#define MMA_BF16(d, a, b0, b1)                                               \
    asm volatile("mma.sync.aligned.m16n8k16.row.col.f32.bf16.bf16.f32 "      \
                 "{%0,%1,%2,%3}, {%4,%5,%6,%7}, {%8,%9}, {%0,%1,%2,%3};\n"   \
                 : "+f"(d[0]), "+f"(d[1]), "+f"(d[2]), "+f"(d[3])            \
                 : "r"(a[0]), "r"(a[1]), "r"(a[2]), "r"(a[3]),               \
                   "r"(b0), "r"(b1))

__device__ __forceinline__ void split_pack(float v0, float v1, uint32_t& hi, uint32_t& lo) {
    __nv_bfloat16 h0 = __float2bfloat16_rn(v0);
    __nv_bfloat16 h1 = __float2bfloat16_rn(v1);
    __nv_bfloat16 l0 = __float2bfloat16_rn(v0 - __bfloat162float(h0));
    __nv_bfloat16 l1 = __float2bfloat16_rn(v1 - __bfloat162float(h1));
    hi = (uint32_t)__bfloat16_as_ushort(h0) | ((uint32_t)__bfloat16_as_ushort(h1) << 16);
    lo = (uint32_t)__bfloat16_as_ushort(l0) | ((uint32_t)__bfloat16_as_ushort(l1) << 16);
}

__global__ __launch_bounds__(256) void bf16_gemm_kernel(
        const float* __restrict__ A, const float* __restrict__ B,
        __half2* __restrict__ C16, int M, int K, int N) {
    __shared__ uint32_t As_hi[2][128 * 9];
    __shared__ uint32_t As_lo[2][128 * 9];
    __shared__ uint32_t Bs_hi[2][128 * 9];
    __shared__ uint32_t Bs_lo[2][128 * 9];

    const int tid  = threadIdx.x;
    const int warp = tid >> 5, lane = tid & 31;
    const int g = lane >> 2, tg = lane & 3;
    const int wy = warp & 3;   // 4 warps along M
    const int wx = warp >> 2;  // 2 warps along N
    const int bm = blockIdx.y * 128, bn = blockIdx.x * 128;

    const int ar = tid >> 1;
    const int ac = (tid & 1) * 8;
    const int kp = warp;            // 0..7 -> k rows 2kp, 2kp+1
    const int n0 = lane * 4;        // 0..124

    float acc[2][8][4];
#pragma unroll
    for (int mt = 0; mt < 2; mt++)
#pragma unroll
        for (int nt = 0; nt < 8; nt++)
#pragma unroll
            for (int c = 0; c < 4; c++) acc[mt][nt][c] = 0.f;

    const int T = K >> 4;
    const bool arow_ok = (bm + ar) < M;

    float4 a0v, a1v, b0v, b1v;
    if (arow_ok) {
        a0v = *(const float4*)(A + (size_t)(bm + ar) * K + ac);
        a1v = *(const float4*)(A + (size_t)(bm + ar) * K + ac + 4);
    } else {
        a0v = a1v = make_float4(0.f, 0.f, 0.f, 0.f);
    }
    b0v = *(const float4*)(B + (size_t)(2 * kp) * N + bn + n0);
    b1v = *(const float4*)(B + (size_t)(2 * kp + 1) * N + bn + n0);
    {
        const int buf = 0;
        const float* a0p = &a0v.x;
        const float* a1p = &a1v.x;
#pragma unroll
        for (int j = 0; j < 2; j++) {
            uint32_t h, l;
            split_pack(a0p[2 * j], a0p[2 * j + 1], h, l);
            As_hi[buf][ar * 9 + (ac >> 1) + j] = h;
            As_lo[buf][ar * 9 + (ac >> 1) + j] = l;
            split_pack(a1p[2 * j], a1p[2 * j + 1], h, l);
            As_hi[buf][ar * 9 + (ac >> 1) + 2 + j] = h;
            As_lo[buf][ar * 9 + (ac >> 1) + 2 + j] = l;
        }
        const float* b0p = &b0v.x;
        const float* b1p = &b1v.x;
#pragma unroll
        for (int j = 0; j < 4; j++) {
            uint32_t h, l;
            split_pack(b0p[j], b1p[j], h, l);
            Bs_hi[buf][(n0 + j) * 9 + kp] = h;
            Bs_lo[buf][(n0 + j) * 9 + kp] = l;
        }
    }
    __syncthreads();

    for (int t = 0; t < T; t++) {
        const int buf = t & 1;
        if (t + 1 < T) {
            int k0 = (t + 1) << 4;
            if (arow_ok) {
                a0v = *(const float4*)(A + (size_t)(bm + ar) * K + k0 + ac);
                a1v = *(const float4*)(A + (size_t)(bm + ar) * K + k0 + ac + 4);
            }
            b0v = *(const float4*)(B + (size_t)(k0 + 2 * kp) * N + bn + n0);
            b1v = *(const float4*)(B + (size_t)(k0 + 2 * kp + 1) * N + bn + n0);
        }

        uint32_t ah[2][4], al[2][4];
#pragma unroll
        for (int mt = 0; mt < 2; mt++) {
            int r0 = (wy * 32 + mt * 16 + g) * 9 + tg;
            int r1 = r0 + 8 * 9;
            ah[mt][0] = As_hi[buf][r0];
            ah[mt][1] = As_hi[buf][r1];
            ah[mt][2] = As_hi[buf][r0 + 4];
            ah[mt][3] = As_hi[buf][r1 + 4];
            al[mt][0] = As_lo[buf][r0];
            al[mt][1] = As_lo[buf][r1];
            al[mt][2] = As_lo[buf][r0 + 4];
            al[mt][3] = As_lo[buf][r1 + 4];
        }
#pragma unroll
        for (int nt = 0; nt < 8; nt++) {
            int ni = (wx * 64 + nt * 8 + g) * 9 + tg;
            uint32_t bh0 = Bs_hi[buf][ni];
            uint32_t bh1 = Bs_hi[buf][ni + 4];
            uint32_t bl0 = Bs_lo[buf][ni];
            uint32_t bl1 = Bs_lo[buf][ni + 4];
#pragma unroll
            for (int mt = 0; mt < 2; mt++) {
                MMA_BF16(acc[mt][nt], ah[mt], bh0, bh1);
                MMA_BF16(acc[mt][nt], ah[mt], bl0, bl1);
                MMA_BF16(acc[mt][nt], al[mt], bh0, bh1);
            }
        }

        if (t + 1 < T) {
            const int nbuf = (t + 1) & 1;
            const float* a0p = &a0v.x;
            const float* a1p = &a1v.x;
#pragma unroll
            for (int j = 0; j < 2; j++) {
                uint32_t h, l;
                split_pack(a0p[2 * j], a0p[2 * j + 1], h, l);
                As_hi[nbuf][ar * 9 + (ac >> 1) + j] = h;
                As_lo[nbuf][ar * 9 + (ac >> 1) + j] = l;
                split_pack(a1p[2 * j], a1p[2 * j + 1], h, l);
                As_hi[nbuf][ar * 9 + (ac >> 1) + 2 + j] = h;
                As_lo[nbuf][ar * 9 + (ac >> 1) + 2 + j] = l;
            }
            const float* b0p = &b0v.x;
            const float* b1p = &b1v.x;
#pragma unroll
            for (int j = 0; j < 4; j++) {
                uint32_t h, l;
                split_pack(b0p[j], b1p[j], h, l);
                Bs_hi[nbuf][(n0 + j) * 9 + kp] = h;
                Bs_lo[nbuf][(n0 + j) * 9 + kp] = l;
            }
        }
        __syncthreads();
    }

    // epilogue: write C as fp16 (half2 per 2 consecutive cols; col even)
#pragma unroll
    for (int mt = 0; mt < 2; mt++) {
        int gr0 = bm + wy * 32 + mt * 16 + g;
        int gr1 = gr0 + 8;
#pragma unroll
        for (int nt = 0; nt < 8; nt++) {
            int col = bn + wx * 64 + nt * 8 + 2 * tg;
            if (gr0 < M)
                C16[((size_t)gr0 * N + col) >> 1] =
                    __floats2half2_rn(acc[mt][nt][0], acc[mt][nt][1]);
            if (gr1 < M)
                C16[((size_t)gr1 * N + col) >> 1] =
                    __floats2half2_rn(acc[mt][nt][2], acc[mt][nt][3]);
        }
    }
}

// ---------------- attention scores: warp per node, fp16 h, half2 lanes -------
// lane owns features f = 2*lane + 64*j (and f+1). head = f >> LOGC.
template<int RJ2, int LOGC>
__global__ void scores_warp_kernel(const __half2* __restrict__ h16,
                                   const float* __restrict__ asrc, const float* __restrict__ adst,
                                   float* __restrict__ esrc, float* __restrict__ edst, int Nn) {
    const int HC2 = RJ2 * 32;   // half2 words per node
    int warp = (blockIdx.x * blockDim.x + threadIdx.x) >> 5;
    int lane = threadIdx.x & 31;
    if (warp >= Nn) return;
    const __half2* hp = h16 + (size_t)warp * HC2 + lane;
    float ps[4] = {0.f, 0.f, 0.f, 0.f};
    float pd[4] = {0.f, 0.f, 0.f, 0.f};
#pragma unroll
    for (int j = 0; j < RJ2; j++) {
        int f = 2 * lane + 64 * j;
        int hd = f >> LOGC;
        float2 v = __half22float2(hp[32 * j]);
        float2 as = *(const float2*)&asrc[f];
        float2 ad = *(const float2*)&adst[f];
        ps[hd] += v.x * as.x + v.y * as.y;
        pd[hd] += v.x * ad.x + v.y * ad.y;
    }
#pragma unroll
    for (int hd = 0; hd < 4; hd++) {
#pragma unroll
        for (int d = 16; d > 0; d >>= 1) {
            ps[hd] += __shfl_xor_sync(0xffffffffu, ps[hd], d);
            pd[hd] += __shfl_xor_sync(0xffffffffu, pd[hd], d);
        }
    }
    if (lane < 4) {
        esrc[warp * 4 + lane] = ps[lane];
        edst[warp * 4 + lane] = pd[lane];
    }
}

// ---------------- fully fused aggregation: warp per dst node, fp16 gather ----
template<int RJ2, int LOGC, int DOELU>
__global__ void gat_agg_kernel(const __half2* __restrict__ h16,
                               const float* __restrict__ esrc, const float* __restrict__ edst,
                               const int* __restrict__ off, const int* __restrict__ csr_src,
                               const float* __restrict__ bias,
                               const float* __restrict__ gam, const float* __restrict__ bet,
                               float* __restrict__ outp, int Nn) {
    const int HC  = RJ2 * 64;
    const int HC2 = RJ2 * 32;
    int n = (blockIdx.x * blockDim.x + threadIdx.x) >> 5;
    int lane = threadIdx.x & 31;
    if (n >= Nn) return;

    int beg = off[n], end = off[n + 1];
    float4 ed = ((const float4*)edst)[n];

    // pass 1: segment max per head
    float m0 = -INFINITY, m1 = -INFINITY, m2 = -INFINITY, m3 = -INFINITY;
    for (int i = beg + lane; i < end; i += 32) {
        int s = csr_src[i];
        float4 es = ((const float4*)esrc)[s];
        float e0 = es.x + ed.x; e0 = e0 > 0.f ? e0 : SLOPE * e0; m0 = fmaxf(m0, e0);
        float e1 = es.y + ed.y; e1 = e1 > 0.f ? e1 : SLOPE * e1; m1 = fmaxf(m1, e1);
        float e2 = es.z + ed.z; e2 = e2 > 0.f ? e2 : SLOPE * e2; m2 = fmaxf(m2, e2);
        float e3 = es.w + ed.w; e3 = e3 > 0.f ? e3 : SLOPE * e3; m3 = fmaxf(m3, e3);
    }
#pragma unroll
    for (int d = 16; d > 0; d >>= 1) {
        m0 = fmaxf(m0, __shfl_xor_sync(0xffffffffu, m0, d));
        m1 = fmaxf(m1, __shfl_xor_sync(0xffffffffu, m1, d));
        m2 = fmaxf(m2, __shfl_xor_sync(0xffffffffu, m2, d));
        m3 = fmaxf(m3, __shfl_xor_sync(0xffffffffu, m3, d));
    }

    // pass 2: p = exp(e-m); denom += p; acc += p * h[src]
    float2 acc2[RJ2];
#pragma unroll
    for (int j = 0; j < RJ2; j++) acc2[j] = make_float2(0.f, 0.f);
    float den0 = 0.f, den1 = 0.f, den2 = 0.f, den3 = 0.f;

    for (int i = beg; i < end; i += 32) {
        int cnt = min(32, end - i);
        int s_l = 0;
        float p0 = 0.f, p1 = 0.f, p2 = 0.f, p3 = 0.f;
        if (lane < cnt) {
            s_l = csr_src[i + lane];
            float4 es = ((const float4*)esrc)[s_l];
            float e0 = es.x + ed.x; e0 = e0 > 0.f ? e0 : SLOPE * e0;
            float e1 = es.y + ed.y; e1 = e1 > 0.f ? e1 : SLOPE * e1;
            float e2 = es.z + ed.z; e2 = e2 > 0.f ? e2 : SLOPE * e2;
            float e3 = es.w + ed.w; e3 = e3 > 0.f ? e3 : SLOPE * e3;
            p0 = __expf(e0 - m0); p1 = __expf(e1 - m1);
            p2 = __expf(e2 - m2); p3 = __expf(e3 - m3);
        }
        for (int k = 0; k < cnt; k++) {
            int   s  = __shfl_sync(0xffffffffu, s_l, k);
            float q0 = __shfl_sync(0xffffffffu, p0, k);
            float q1 = __shfl_sync(0xffffffffu, p1, k);
            float q2 = __shfl_sync(0xffffffffu, p2, k);
            float q3 = __shfl_sync(0xffffffffu, p3, k);
            den0 += q0; den1 += q1; den2 += q2; den3 += q3;
            float q[4] = {q0, q1, q2, q3};
            const __half2* row = h16 + (size_t)s * HC2 + lane;
#pragma unroll
            for (int j = 0; j < RJ2; j++) {
                int hd = (2 * lane + 64 * j) >> LOGC;
                float2 fv = __half22float2(row[32 * j]);
                acc2[j].x += q[hd] * fv.x;
                acc2[j].y += q[hd] * fv.y;
            }
        }
    }

    // epilogue in registers
    float den[4] = {den0, den1, den2, den3};
    float2 vals[RJ2];
    float sum = 0.f;
#pragma unroll
    for (int j = 0; j < RJ2; j++) {
        int f = 2 * lane + 64 * j;
        int hd = f >> LOGC;
        float2 b = *(const float2*)&bias[f];
        float vx = acc2[j].x / den[hd] + b.x;
        float vy = acc2[j].y / den[hd] + b.y;
        if (DOELU) {
            vx = vx > 0.f ? vx : expm1f(vx);
            vy = vy > 0.f ? vy : expm1f(vy);
        }
        vals[j] = make_float2(vx, vy);
        sum += vx + vy;
    }
#pragma unroll
    for (int d = 16; d > 0; d >>= 1) sum += __shfl_xor_sync(0xffffffffu, sum, d);
    float mu = sum / (float)HC;
    float vs = 0.f;
#pragma unroll
    for (int j = 0; j < RJ2; j++) {
        float dx = vals[j].x - mu, dy = vals[j].y - mu;
        vs += dx * dx + dy * dy;
    }
#pragma unroll
    for (int d = 16; d > 0; d >>= 1) vs += __shfl_xor_sync(0xffffffffu, vs, d);
    float rstd = rsqrtf(vs / (float)HC + LN_EPS);
#pragma unroll
    for (int j = 0; j < RJ2; j++) {
        int f = 2 * lane + 64 * j;
        float2 gm = *(const float2*)&gam[f];
        float2 bt = *(const float2*)&bet[f];
        float2 o;
        o.x = gm.x * (vals[j].x - mu) * rstd + bt.x;
        o.y = gm.y * (vals[j].y - mu) * rstd + bt.y;
        *(float2*)&outp[(size_t)n * HC + f] = o;
    }
}

// ---------------- mean pool: block per graph, binary search (batch sorted) ---
__global__ void pool_kernel(const float* __restrict__ node_out, const int* __restrict__ batch,
                            float* __restrict__ graph_out, int Nn) {
    int g = blockIdx.x;
    int f = threadIdx.x;  // 128
    int lo = 0, hi = Nn;
    while (lo < hi) { int mid = (lo + hi) >> 1; if (batch[mid] < g) lo = mid + 1; else hi = mid; }
    int start = lo;
    lo = start; hi = Nn;
    while (lo < hi) { int mid = (lo + hi) >> 1; if (batch[mid] < g + 1) lo = mid + 1; else hi = mid; }
    int end = lo;
    float s = 0.f;
    for (int n = start; n < end; n++) s += node_out[(size_t)n * 128 + f];
    graph_out[g * 128 + f] = s / fmaxf((float)(end - start), 1.f);
}

// ---------------- launch -----------------------------------------------------
extern "C" void kernel_launch(void* const* d_in, const int* in_sizes, int n_in,
                              void* d_out, int out_size) {
    const float* x     = (const float*)d_in[0];
    const int*   ei    = (const int*)d_in[1];
    const int*   batch = (const int*)d_in[2];
    const float* W[3]    = {(const float*)d_in[3],  (const float*)d_in[9],  (const float*)d_in[15]};
    const float* asrc[3] = {(const float*)d_in[4],  (const float*)d_in[10], (const float*)d_in[16]};
    const float* adst[3] = {(const float*)d_in[5],  (const float*)d_in[11], (const float*)d_in[17]};
    const float* bia[3]  = {(const float*)d_in[6],  (const float*)d_in[12], (const float*)d_in[18]};
    const float* gam[3]  = {(const float*)d_in[7],  (const float*)d_in[13], (const float*)d_in[19]};
    const float* bet[3]  = {(const float*)d_in[8],  (const float*)d_in[14], (const float*)d_in[20]};

    int N = in_sizes[0] / 768;
    int E = in_sizes[1] / 2;
    int Etot = E + N;
    const int* srcA = ei;
    const int* dstA = ei + E;

    float* node_out  = (float*)d_out;
    float* graph_out = node_out + (size_t)N * 128;

    __half2* p_h16;
    float *p_in, *p_esrc, *p_edst;
    int *p_deg, *p_off, *p_cur, *p_csr;
    cudaGetSymbolAddress((void**)&p_h16, g_h16);
    cudaGetSymbolAddress((void**)&p_in, g_in);
    cudaGetSymbolAddress((void**)&p_esrc, g_esrc);
    cudaGetSymbolAddress((void**)&p_edst, g_edst);
    cudaGetSymbolAddress((void**)&p_deg, g_deg);
    cudaGetSymbolAddress((void**)&p_off, g_off);
    cudaGetSymbolAddress((void**)&p_cur, g_cur);
    cudaGetSymbolAddress((void**)&p_csr, g_csr);

    // ---- build dst-CSR once (shared across all 3 layers) ----
    init_deg_kernel<<<(N + 255) / 256, 256>>>(p_deg, p_cur, N);
    deg_hist_kernel<<<(E + 255) / 256, 256>>>(dstA, E, p_deg);
    scan_kernel<<<1, 1024>>>(p_deg, p_off, N);
    csr_scatter_kernel<<<(Etot + 255) / 256, 256>>>(srcA, dstA, E, Etot, p_off, p_cur, p_csr);

    int dins[3] = {768, 256, 256};
    int HCs[3]  = {256, 256, 128};
    const float* inputs[3] = {x, p_in, p_in};
    float* outs[3] = {p_in, p_in, node_out};

    for (int L = 0; L < 3; L++) {
        int K = dins[L], HC = HCs[L];

        dim3 ggrid(HC / 128, (N + 127) / 128);
        bf16_gemm_kernel<<<ggrid, 256>>>(inputs[L], W[L], p_h16, N, K, HC);

        int nwb = (N + 7) / 8;   // 8 warps / block
        if (HC == 256) {
            scores_warp_kernel<4, 6><<<nwb, 256>>>(p_h16, asrc[L], adst[L], p_esrc, p_edst, N);
            if (L < 2)
                gat_agg_kernel<4, 6, 1><<<nwb, 256>>>(p_h16, p_esrc, p_edst, p_off, p_csr,
                                                      bia[L], gam[L], bet[L], outs[L], N);
            else
                gat_agg_kernel<4, 6, 0><<<nwb, 256>>>(p_h16, p_esrc, p_edst, p_off, p_csr,
                                                      bia[L], gam[L], bet[L], outs[L], N);
        } else {
            scores_warp_kernel<2, 5><<<nwb, 256>>>(p_h16, asrc[L], adst[L], p_esrc, p_edst, N);
            gat_agg_kernel<2, 5, 0><<<nwb, 256>>>(p_h16, p_esrc, p_edst, p_off, p_csr,
                                                  bia[L], gam[L], bet[L], outs[L], N);
        }
    }

    pool_kernel<<<GMAX, 128>>>(node_out, batch, graph_out, N);
}

// round 9
// speedup vs baseline: 2.7824x; 1.1778x over previous
#include <cuda_runtime.h>
#include <cuda_fp16.h>
#include <math.h>
#include <stdint.h>

#define NMAX 50000
#define EMAX 800000
#define ETOTMAX (EMAX + NMAX)
#define GMAX 64
#define LN_EPS 1e-5f
#define SLOPE 0.2f

// ---------------- scratch (static device globals; no runtime alloc) ----------
__device__ __half2 g_h16[(size_t)NMAX * 128];  // GEMM output, fp16 (256 halves/node)
__device__ float g_in  [(size_t)NMAX * 256];   // normalized features (input to next layer)
__device__ float g_esrc[NMAX * 4];
__device__ float g_edst[NMAX * 4];
__device__ int   g_deg [NMAX + 1];
__device__ int   g_off [NMAX + 1];
__device__ int   g_cur [NMAX];
__device__ int   g_csr [ETOTMAX];

// ---------------- CSR build --------------------------------------------------
__global__ void init_deg_kernel(int* __restrict__ deg, int* __restrict__ cur, int Nn) {
    int i = blockIdx.x * blockDim.x + threadIdx.x;
    if (i < Nn) { deg[i] = 1; cur[i] = 0; }   // deg starts at 1: self-loop
}

__global__ void deg_hist_kernel(const int* __restrict__ dst, int E_, int* __restrict__ deg) {
    int i = blockIdx.x * blockDim.x + threadIdx.x;
    if (i < E_) atomicAdd(&deg[dst[i]], 1);
}

// single-block exclusive scan over n ints: warp-scan + carry loop
__global__ void scan_kernel(const int* __restrict__ deg, int* __restrict__ off, int n) {
    __shared__ int warp_sums[32];
    __shared__ int s_carry;
    int tid = threadIdx.x;           // 1024 threads
    int lane = tid & 31, wid = tid >> 5;
    if (tid == 0) s_carry = 0;
    __syncthreads();
    for (int base = 0; base < n; base += 1024) {
        int idx = base + tid;
        int v = (idx < n) ? deg[idx] : 0;
        int incl = v;
#pragma unroll
        for (int d = 1; d < 32; d <<= 1) {
            int t = __shfl_up_sync(0xffffffffu, incl, d);
            if (lane >= d) incl += t;
        }
        if (lane == 31) warp_sums[wid] = incl;
        __syncthreads();
        if (wid == 0) {
            int ws = warp_sums[lane];
            int wincl = ws;
#pragma unroll
            for (int d = 1; d < 32; d <<= 1) {
                int t = __shfl_up_sync(0xffffffffu, wincl, d);
                if (lane >= d) wincl += t;
            }
            warp_sums[lane] = wincl - ws;   // exclusive prefix of warp sums
        }
        __syncthreads();
        int carry = s_carry;
        if (idx < n) off[idx] = carry + warp_sums[wid] + incl - v;
        __syncthreads();
        if (tid == 1023) s_carry = carry + warp_sums[31] + incl;
        __syncthreads();
    }
    if (tid == 0) off[n] = s_carry;
}

__global__ void csr_scatter_kernel(const int* __restrict__ src, const int* __restrict__ dst,
                                   int E_, int Etot,
                                   const int* __restrict__ off, int* __restrict__ cur,
                                   int* __restrict__ csr_src) {
    int i = blockIdx.x * blockDim.x + threadIdx.x;
    if (i >= Etot) return;
    int s, d;
    if (i < E_) { s = src[i]; d = dst[i]; } else { s = d = i - E_; }
    int pos = off[d] + atomicAdd(&cur[d], 1);
    csr_src[pos] = s;
}

// ---------------- fp16 tensor-core GEMM, A hi/lo split (2xF16) ---------------
// C16[M,N] (fp16) = A[M,K] @ B[K,N]:  A = Ahi + Alo (fp16 pair -> A full prec),
// B rounded once to fp16 (error ~2^-12, the only GEMM error source).
//   C = Ahi*Bhi + Alo*Bhi
// Block tile 128x128, BK=16, double-buffered smem, 8 warps @ 32x64 warp tiles.
// Fused epilogue: attention scores esrc/edst (per-head dot with asrc/adst)
// computed from fp32 accumulators; warp's 64-col slice = whole head(s).

#define MMA_F16(d, a, b0, b1)                                                \
    asm volatile("mma.sync.aligned.m16n8k16.row.col.f32.f16.f16.f32 "        \
                 "{%0,%1,%2,%3}, {%4,%5,%6,%7}, {%8,%9}, {%0,%1,%2,%3};\n"   \
                 : "+f"(d[0]), "+f"(d[1]), "+f"(d[2]), "+f"(d[3])            \
                 : "r"(a[0]), "r"(a[1]), "r"(a[2]), "r"(a[3]),               \
                   "r"(b0), "r"(b1))

__device__ __forceinline__ void split_pack_f16(float v0, float v1, uint32_t& hi, uint32_t& lo) {
    __half h0 = __float2half_rn(v0);
    __half h1 = __float2half_rn(v1);
    __half l0 = __float2half_rn(v0 - __half2float(h0));
    __half l1 = __float2half_rn(v1 - __half2float(h1));
    hi = (uint32_t)__half_as_ushort(h0) | ((uint32_t)__half_as_ushort(h1) << 16);
    lo = (uint32_t)__half_as_ushort(l0) | ((uint32_t)__half_as_ushort(l1) << 16);
}

__device__ __forceinline__ uint32_t pack_f16(float v0, float v1) {
    __half h0 = __float2half_rn(v0);
    __half h1 = __float2half_rn(v1);
    return (uint32_t)__half_as_ushort(h0) | ((uint32_t)__half_as_ushort(h1) << 16);
}

// LOGC: log2(head width). HC=256 -> 6 (1 head per 64-col warp slice);
//       HC=128 -> 5 (2 heads per warp slice).
template<int LOGC>
__global__ __launch_bounds__(256) void f16_gemm_scores_kernel(
        const float* __restrict__ A, const float* __restrict__ B,
        __half2* __restrict__ C16,
        const float* __restrict__ asrc, const float* __restrict__ adst,
        float* __restrict__ esrc, float* __restrict__ edst,
        int M, int K, int N) {
    __shared__ uint32_t As_hi[2][128 * 9];
    __shared__ uint32_t As_lo[2][128 * 9];
    __shared__ uint32_t Bs_hi[2][128 * 9];

    const int tid  = threadIdx.x;
    const int warp = tid >> 5, lane = tid & 31;
    const int g = lane >> 2, tg = lane & 3;
    const int wy = warp & 3;   // 4 warps along M
    const int wx = warp >> 2;  // 2 warps along N
    const int bm = blockIdx.y * 128, bn = blockIdx.x * 128;

    const int ar = tid >> 1;
    const int ac = (tid & 1) * 8;
    const int kp = warp;            // 0..7 -> k rows 2kp, 2kp+1
    const int n0 = lane * 4;        // 0..124

    float acc[2][8][4];
#pragma unroll
    for (int mt = 0; mt < 2; mt++)
#pragma unroll
        for (int nt = 0; nt < 8; nt++)
#pragma unroll
            for (int c = 0; c < 4; c++) acc[mt][nt][c] = 0.f;

    const int T = K >> 4;
    const bool arow_ok = (bm + ar) < M;

    float4 a0v, a1v, b0v, b1v;
    if (arow_ok) {
        a0v = *(const float4*)(A + (size_t)(bm + ar) * K + ac);
        a1v = *(const float4*)(A + (size_t)(bm + ar) * K + ac + 4);
    } else {
        a0v = a1v = make_float4(0.f, 0.f, 0.f, 0.f);
    }
    b0v = *(const float4*)(B + (size_t)(2 * kp) * N + bn + n0);
    b1v = *(const float4*)(B + (size_t)(2 * kp + 1) * N + bn + n0);
    {
        const int buf = 0;
        const float* a0p = &a0v.x;
        const float* a1p = &a1v.x;
#pragma unroll
        for (int j = 0; j < 2; j++) {
            uint32_t h, l;
            split_pack_f16(a0p[2 * j], a0p[2 * j + 1], h, l);
            As_hi[buf][ar * 9 + (ac >> 1) + j] = h;
            As_lo[buf][ar * 9 + (ac >> 1) + j] = l;
            split_pack_f16(a1p[2 * j], a1p[2 * j + 1], h, l);
            As_hi[buf][ar * 9 + (ac >> 1) + 2 + j] = h;
            As_lo[buf][ar * 9 + (ac >> 1) + 2 + j] = l;
        }
        const float* b0p = &b0v.x;
        const float* b1p = &b1v.x;
#pragma unroll
        for (int j = 0; j < 4; j++)
            Bs_hi[buf][(n0 + j) * 9 + kp] = pack_f16(b0p[j], b1p[j]);
    }
    __syncthreads();

    for (int t = 0; t < T; t++) {
        const int buf = t & 1;
        if (t + 1 < T) {
            int k0 = (t + 1) << 4;
            if (arow_ok) {
                a0v = *(const float4*)(A + (size_t)(bm + ar) * K + k0 + ac);
                a1v = *(const float4*)(A + (size_t)(bm + ar) * K + k0 + ac + 4);
            }
            b0v = *(const float4*)(B + (size_t)(k0 + 2 * kp) * N + bn + n0);
            b1v = *(const float4*)(B + (size_t)(k0 + 2 * kp + 1) * N + bn + n0);
        }

        uint32_t ah[2][4], al[2][4];
#pragma unroll
        for (int mt = 0; mt < 2; mt++) {
            int r0 = (wy * 32 + mt * 16 + g) * 9 + tg;
            int r1 = r0 + 8 * 9;
            ah[mt][0] = As_hi[buf][r0];
            ah[mt][1] = As_hi[buf][r1];
            ah[mt][2] = As_hi[buf][r0 + 4];
            ah[mt][3] = As_hi[buf][r1 + 4];
            al[mt][0] = As_lo[buf][r0];
            al[mt][1] = As_lo[buf][r1];
            al[mt][2] = As_lo[buf][r0 + 4];
            al[mt][3] = As_lo[buf][r1 + 4];
        }
#pragma unroll
        for (int nt = 0; nt < 8; nt++) {
            int ni = (wx * 64 + nt * 8 + g) * 9 + tg;
            uint32_t bh0 = Bs_hi[buf][ni];
            uint32_t bh1 = Bs_hi[buf][ni + 4];
#pragma unroll
            for (int mt = 0; mt < 2; mt++) {
                MMA_F16(acc[mt][nt], ah[mt], bh0, bh1);
                MMA_F16(acc[mt][nt], al[mt], bh0, bh1);
            }
        }

        if (t + 1 < T) {
            const int nbuf = (t + 1) & 1;
            const float* a0p = &a0v.x;
            const float* a1p = &a1v.x;
#pragma unroll
            for (int j = 0; j < 2; j++) {
                uint32_t h, l;
                split_pack_f16(a0p[2 * j], a0p[2 * j + 1], h, l);
                As_hi[nbuf][ar * 9 + (ac >> 1) + j] = h;
                As_lo[nbuf][ar * 9 + (ac >> 1) + j] = l;
                split_pack_f16(a1p[2 * j], a1p[2 * j + 1], h, l);
                As_hi[nbuf][ar * 9 + (ac >> 1) + 2 + j] = h;
                As_lo[nbuf][ar * 9 + (ac >> 1) + 2 + j] = l;
            }
            const float* b0p = &b0v.x;
            const float* b1p = &b1v.x;
#pragma unroll
            for (int j = 0; j < 4; j++)
                Bs_hi[nbuf][(n0 + j) * 9 + kp] = pack_f16(b0p[j], b1p[j]);
        }
        __syncthreads();
    }

    // ---- epilogue 1: write C as fp16 ----
#pragma unroll
    for (int mt = 0; mt < 2; mt++) {
        int gr0 = bm + wy * 32 + mt * 16 + g;
        int gr1 = gr0 + 8;
#pragma unroll
        for (int nt = 0; nt < 8; nt++) {
            int col = bn + wx * 64 + nt * 8 + 2 * tg;
            if (gr0 < M)
                C16[((size_t)gr0 * N + col) >> 1] =
                    __floats2half2_rn(acc[mt][nt][0], acc[mt][nt][1]);
            if (gr1 < M)
                C16[((size_t)gr1 * N + col) >> 1] =
                    __floats2half2_rn(acc[mt][nt][2], acc[mt][nt][3]);
        }
    }

    // ---- epilogue 2: fused attention scores ----
    // partials [mt][rowhalf][headslot]; headslot: 1 slot (LOGC=6) or 2 (LOGC=5)
    const int NSLOT = (LOGC == 6) ? 1 : 2;
    float psrc[2][2][2] = {};
    float pdst[2][2][2] = {};
#pragma unroll
    for (int nt = 0; nt < 8; nt++) {
        int gc = bn + wx * 64 + nt * 8 + 2 * tg;
        float2 as = *(const float2*)&asrc[gc];
        float2 ad = *(const float2*)&adst[gc];
        int hs = (LOGC == 6) ? 0 : (nt >> 2);
#pragma unroll
        for (int mt = 0; mt < 2; mt++) {
            psrc[mt][0][hs] += acc[mt][nt][0] * as.x + acc[mt][nt][1] * as.y;
            psrc[mt][1][hs] += acc[mt][nt][2] * as.x + acc[mt][nt][3] * as.y;
            pdst[mt][0][hs] += acc[mt][nt][0] * ad.x + acc[mt][nt][1] * ad.y;
            pdst[mt][1][hs] += acc[mt][nt][2] * ad.x + acc[mt][nt][3] * ad.y;
        }
    }
    // quad reduction (lanes differing in tg = lane bits 0,1)
#pragma unroll
    for (int mt = 0; mt < 2; mt++)
#pragma unroll
        for (int rh = 0; rh < 2; rh++)
#pragma unroll
            for (int hs = 0; hs < NSLOT; hs++) {
                float s1 = psrc[mt][rh][hs], s2 = pdst[mt][rh][hs];
                s1 += __shfl_xor_sync(0xffffffffu, s1, 1);
                s1 += __shfl_xor_sync(0xffffffffu, s1, 2);
                s2 += __shfl_xor_sync(0xffffffffu, s2, 1);
                s2 += __shfl_xor_sync(0xffffffffu, s2, 2);
                psrc[mt][rh][hs] = s1;
                pdst[mt][rh][hs] = s2;
            }
    if (tg == 0) {
#pragma unroll
        for (int mt = 0; mt < 2; mt++)
#pragma unroll
            for (int rh = 0; rh < 2; rh++) {
                int gr = bm + wy * 32 + mt * 16 + g + rh * 8;
                if (gr < M) {
#pragma unroll
                    for (int hs = 0; hs < NSLOT; hs++) {
                        int hd = (LOGC == 6) ? ((bn >> 6) + wx) : (wx * 2 + hs);
                        esrc[gr * 4 + hd] = psrc[mt][rh][hs];
                        edst[gr * 4 + hd] = pdst[mt][rh][hs];
                    }
                }
            }
    }
}

// ---------------- fully fused aggregation: warp per dst node, fp16 gather ----
template<int RJ2, int LOGC, int DOELU>
__global__ void gat_agg_kernel(const __half2* __restrict__ h16,
                               const float* __restrict__ esrc, const float* __restrict__ edst,
                               const int* __restrict__ off, const int* __restrict__ csr_src,
                               const float* __restrict__ bias,
                               const float* __restrict__ gam, const float* __restrict__ bet,
                               float* __restrict__ outp, int Nn) {
    const int HC  = RJ2 * 64;
    const int HC2 = RJ2 * 32;
    int n = (blockIdx.x * blockDim.x + threadIdx.x) >> 5;
    int lane = threadIdx.x & 31;
    if (n >= Nn) return;

    int beg = off[n], end = off[n + 1];
    float4 ed = ((const float4*)edst)[n];

    // pass 1: segment max per head
    float m0 = -INFINITY, m1 = -INFINITY, m2 = -INFINITY, m3 = -INFINITY;
    for (int i = beg + lane; i < end; i += 32) {
        int s = csr_src[i];
        float4 es = ((const float4*)esrc)[s];
        float e0 = es.x + ed.x; e0 = e0 > 0.f ? e0 : SLOPE * e0; m0 = fmaxf(m0, e0);
        float e1 = es.y + ed.y; e1 = e1 > 0.f ? e1 : SLOPE * e1; m1 = fmaxf(m1, e1);
        float e2 = es.z + ed.z; e2 = e2 > 0.f ? e2 : SLOPE * e2; m2 = fmaxf(m2, e2);
        float e3 = es.w + ed.w; e3 = e3 > 0.f ? e3 : SLOPE * e3; m3 = fmaxf(m3, e3);
    }
#pragma unroll
    for (int d = 16; d > 0; d >>= 1) {
        m0 = fmaxf(m0, __shfl_xor_sync(0xffffffffu, m0, d));
        m1 = fmaxf(m1, __shfl_xor_sync(0xffffffffu, m1, d));
        m2 = fmaxf(m2, __shfl_xor_sync(0xffffffffu, m2, d));
        m3 = fmaxf(m3, __shfl_xor_sync(0xffffffffu, m3, d));
    }

    // pass 2: p = exp(e-m); denom += p; acc += p * h[src]
    float2 acc2[RJ2];
#pragma unroll
    for (int j = 0; j < RJ2; j++) acc2[j] = make_float2(0.f, 0.f);
    float den0 = 0.f, den1 = 0.f, den2 = 0.f, den3 = 0.f;

    for (int i = beg; i < end; i += 32) {
        int cnt = min(32, end - i);
        int s_l = 0;
        float p0 = 0.f, p1 = 0.f, p2 = 0.f, p3 = 0.f;
        if (lane < cnt) {
            s_l = csr_src[i + lane];
            float4 es = ((const float4*)esrc)[s_l];
            float e0 = es.x + ed.x; e0 = e0 > 0.f ? e0 : SLOPE * e0;
            float e1 = es.y + ed.y; e1 = e1 > 0.f ? e1 : SLOPE * e1;
            float e2 = es.z + ed.z; e2 = e2 > 0.f ? e2 : SLOPE * e2;
            float e3 = es.w + ed.w; e3 = e3 > 0.f ? e3 : SLOPE * e3;
            p0 = __expf(e0 - m0); p1 = __expf(e1 - m1);
            p2 = __expf(e2 - m2); p3 = __expf(e3 - m3);
        }
        for (int k = 0; k < cnt; k++) {
            int   s  = __shfl_sync(0xffffffffu, s_l, k);
            float q0 = __shfl_sync(0xffffffffu, p0, k);
            float q1 = __shfl_sync(0xffffffffu, p1, k);
            float q2 = __shfl_sync(0xffffffffu, p2, k);
            float q3 = __shfl_sync(0xffffffffu, p3, k);
            den0 += q0; den1 += q1; den2 += q2; den3 += q3;
            float q[4] = {q0, q1, q2, q3};
            const __half2* row = h16 + (size_t)s * HC2 + lane;
#pragma unroll
            for (int j = 0; j < RJ2; j++) {
                int hd = (2 * lane + 64 * j) >> LOGC;
                float2 fv = __half22float2(row[32 * j]);
                acc2[j].x += q[hd] * fv.x;
                acc2[j].y += q[hd] * fv.y;
            }
        }
    }

    // epilogue in registers
    float den[4] = {den0, den1, den2, den3};
    float2 vals[RJ2];
    float sum = 0.f;
#pragma unroll
    for (int j = 0; j < RJ2; j++) {
        int f = 2 * lane + 64 * j;
        int hd = f >> LOGC;
        float2 b = *(const float2*)&bias[f];
        float vx = acc2[j].x / den[hd] + b.x;
        float vy = acc2[j].y / den[hd] + b.y;
        if (DOELU) {
            vx = vx > 0.f ? vx : expm1f(vx);
            vy = vy > 0.f ? vy : expm1f(vy);
        }
        vals[j] = make_float2(vx, vy);
        sum += vx + vy;
    }
#pragma unroll
    for (int d = 16; d > 0; d >>= 1) sum += __shfl_xor_sync(0xffffffffu, sum, d);
    float mu = sum / (float)HC;
    float vs = 0.f;
#pragma unroll
    for (int j = 0; j < RJ2; j++) {
        float dx = vals[j].x - mu, dy = vals[j].y - mu;
        vs += dx * dx + dy * dy;
    }
#pragma unroll
    for (int d = 16; d > 0; d >>= 1) vs += __shfl_xor_sync(0xffffffffu, vs, d);
    float rstd = rsqrtf(vs / (float)HC + LN_EPS);
#pragma unroll
    for (int j = 0; j < RJ2; j++) {
        int f = 2 * lane + 64 * j;
        float2 gm = *(const float2*)&gam[f];
        float2 bt = *(const float2*)&bet[f];
        float2 o;
        o.x = gm.x * (vals[j].x - mu) * rstd + bt.x;
        o.y = gm.y * (vals[j].y - mu) * rstd + bt.y;
        *(float2*)&outp[(size_t)n * HC + f] = o;
    }
}

// ---------------- mean pool: block per graph, binary search (batch sorted) ---
__global__ void pool_kernel(const float* __restrict__ node_out, const int* __restrict__ batch,
                            float* __restrict__ graph_out, int Nn) {
    int g = blockIdx.x;
    int f = threadIdx.x;  // 128
    int lo = 0, hi = Nn;
    while (lo < hi) { int mid = (lo + hi) >> 1; if (batch[mid] < g) lo = mid + 1; else hi = mid; }
    int start = lo;
    lo = start; hi = Nn;
    while (lo < hi) { int mid = (lo + hi) >> 1; if (batch[mid] < g + 1) lo = mid + 1; else hi = mid; }
    int end = lo;
    float s = 0.f;
    for (int n = start; n < end; n++) s += node_out[(size_t)n * 128 + f];
    graph_out[g * 128 + f] = s / fmaxf((float)(end - start), 1.f);
}

// ---------------- launch -----------------------------------------------------
extern "C" void kernel_launch(void* const* d_in, const int* in_sizes, int n_in,
                              void* d_out, int out_size) {
    const float* x     = (const float*)d_in[0];
    const int*   ei    = (const int*)d_in[1];
    const int*   batch = (const int*)d_in[2];
    const float* W[3]    = {(const float*)d_in[3],  (const float*)d_in[9],  (const float*)d_in[15]};
    const float* asrc[3] = {(const float*)d_in[4],  (const float*)d_in[10], (const float*)d_in[16]};
    const float* adst[3] = {(const float*)d_in[5],  (const float*)d_in[11], (const float*)d_in[17]};
    const float* bia[3]  = {(const float*)d_in[6],  (const float*)d_in[12], (const float*)d_in[18]};
    const float* gam[3]  = {(const float*)d_in[7],  (const float*)d_in[13], (const float*)d_in[19]};
    const float* bet[3]  = {(const float*)d_in[8],  (const float*)d_in[14], (const float*)d_in[20]};

    int N = in_sizes[0] / 768;
    int E = in_sizes[1] / 2;
    int Etot = E + N;
    const int* srcA = ei;
    const int* dstA = ei + E;

    float* node_out  = (float*)d_out;
    float* graph_out = node_out + (size_t)N * 128;

    __half2* p_h16;
    float *p_in, *p_esrc, *p_edst;
    int *p_deg, *p_off, *p_cur, *p_csr;
    cudaGetSymbolAddress((void**)&p_h16, g_h16);
    cudaGetSymbolAddress((void**)&p_in, g_in);
    cudaGetSymbolAddress((void**)&p_esrc, g_esrc);
    cudaGetSymbolAddress((void**)&p_edst, g_edst);
    cudaGetSymbolAddress((void**)&p_deg, g_deg);
    cudaGetSymbolAddress((void**)&p_off, g_off);
    cudaGetSymbolAddress((void**)&p_cur, g_cur);
    cudaGetSymbolAddress((void**)&p_csr, g_csr);

    // ---- build dst-CSR once (shared across all 3 layers) ----
    init_deg_kernel<<<(N + 255) / 256, 256>>>(p_deg, p_cur, N);
    deg_hist_kernel<<<(E + 255) / 256, 256>>>(dstA, E, p_deg);
    scan_kernel<<<1, 1024>>>(p_deg, p_off, N);
    csr_scatter_kernel<<<(Etot + 255) / 256, 256>>>(srcA, dstA, E, Etot, p_off, p_cur, p_csr);

    int dins[3] = {768, 256, 256};
    int HCs[3]  = {256, 256, 128};
    const float* inputs[3] = {x, p_in, p_in};
    float* outs[3] = {p_in, p_in, node_out};

    for (int L = 0; L < 3; L++) {
        int K = dins[L], HC = HCs[L];

        dim3 ggrid(HC / 128, (N + 127) / 128);
        int nwb = (N + 7) / 8;   // 8 warps / block for agg

        if (HC == 256) {
            f16_gemm_scores_kernel<6><<<ggrid, 256>>>(inputs[L], W[L], p_h16,
                                                      asrc[L], adst[L], p_esrc, p_edst,
                                                      N, K, HC);
            if (L < 2)
                gat_agg_kernel<4, 6, 1><<<nwb, 256>>>(p_h16, p_esrc, p_edst, p_off, p_csr,
                                                      bia[L], gam[L], bet[L], outs[L], N);
            else
                gat_agg_kernel<4, 6, 0><<<nwb, 256>>>(p_h16, p_esrc, p_edst, p_off, p_csr,
                                                      bia[L], gam[L], bet[L], outs[L], N);
        } else {
            f16_gemm_scores_kernel<5><<<ggrid, 256>>>(inputs[L], W[L], p_h16,
                                                      asrc[L], adst[L], p_esrc, p_edst,
                                                      N, K, HC);
            gat_agg_kernel<2, 5, 0><<<nwb, 256>>>(p_h16, p_esrc, p_edst, p_off, p_csr,
                                                  bia[L], gam[L], bet[L], outs[L], N);
        }
    }

    pool_kernel<<<GMAX, 128>>>(node_out, batch, graph_out, N);
}

// round 10
// speedup vs baseline: 3.2268x; 1.1597x over previous
#include <cuda_runtime.h>
#include <cuda_fp16.h>
#include <math.h>
#include <stdint.h>

#define NMAX 50000
#define EMAX 800000
#define ETOTMAX (EMAX + NMAX)
#define GMAX 64
#define LN_EPS 1e-5f
#define SLOPE 0.2f

// ---------------- scratch (static device globals; no runtime alloc) ----------
__device__ uint4 g_h16_raw[(size_t)NMAX * 32];  // fp16 features, 16B-aligned (256 halves/node)
__device__ float g_in  [(size_t)NMAX * 256];    // normalized features (input to next layer)
__device__ float g_esrc[NMAX * 4];
__device__ float g_edst[NMAX * 4];
__device__ int   g_deg [NMAX + 1];
__device__ int   g_off [NMAX + 1];
__device__ int   g_cur [NMAX];
__device__ int   g_csr [ETOTMAX];

// ---------------- CSR build --------------------------------------------------
__global__ void init_deg_kernel(int* __restrict__ deg, int* __restrict__ cur, int Nn) {
    int i = blockIdx.x * blockDim.x + threadIdx.x;
    if (i < Nn) { deg[i] = 1; cur[i] = 0; }   // deg starts at 1: self-loop
}

__global__ void deg_hist_kernel(const int* __restrict__ dst, int E_, int* __restrict__ deg) {
    int i = blockIdx.x * blockDim.x + threadIdx.x;
    if (i < E_) atomicAdd(&deg[dst[i]], 1);
}

// single-block exclusive scan over n ints: warp-scan + carry loop
__global__ void scan_kernel(const int* __restrict__ deg, int* __restrict__ off, int n) {
    __shared__ int warp_sums[32];
    __shared__ int s_carry;
    int tid = threadIdx.x;           // 1024 threads
    int lane = tid & 31, wid = tid >> 5;
    if (tid == 0) s_carry = 0;
    __syncthreads();
    for (int base = 0; base < n; base += 1024) {
        int idx = base + tid;
        int v = (idx < n) ? deg[idx] : 0;
        int incl = v;
#pragma unroll
        for (int d = 1; d < 32; d <<= 1) {
            int t = __shfl_up_sync(0xffffffffu, incl, d);
            if (lane >= d) incl += t;
        }
        if (lane == 31) warp_sums[wid] = incl;
        __syncthreads();
        if (wid == 0) {
            int ws = warp_sums[lane];
            int wincl = ws;
#pragma unroll
            for (int d = 1; d < 32; d <<= 1) {
                int t = __shfl_up_sync(0xffffffffu, wincl, d);
                if (lane >= d) wincl += t;
            }
            warp_sums[lane] = wincl - ws;   // exclusive prefix of warp sums
        }
        __syncthreads();
        int carry = s_carry;
        if (idx < n) off[idx] = carry + warp_sums[wid] + incl - v;
        __syncthreads();
        if (tid == 1023) s_carry = carry + warp_sums[31] + incl;
        __syncthreads();
    }
    if (tid == 0) off[n] = s_carry;
}

__global__ void csr_scatter_kernel(const int* __restrict__ src, const int* __restrict__ dst,
                                   int E_, int Etot,
                                   const int* __restrict__ off, int* __restrict__ cur,
                                   int* __restrict__ csr_src) {
    int i = blockIdx.x * blockDim.x + threadIdx.x;
    if (i >= Etot) return;
    int s, d;
    if (i < E_) { s = src[i]; d = dst[i]; } else { s = d = i - E_; }
    int pos = off[d] + atomicAdd(&cur[d], 1);
    csr_src[pos] = s;
}

// ---------------- fp16 tensor-core GEMM, A hi/lo split (2xF16) ---------------
// C16[M,N] (fp16) = A[M,K] @ B[K,N]:  A = Ahi + Alo (fp16 pair -> A full prec),
// B rounded once to fp16. C = Ahi*Bhi + Alo*Bhi.
// Block tile 128x128, BK=16, double-buffered smem, 8 warps @ 32x64 warp tiles.
// Fused epilogue: attention scores esrc/edst from fp32 accumulators.

#define MMA_F16(d, a, b0, b1)                                                \
    asm volatile("mma.sync.aligned.m16n8k16.row.col.f32.f16.f16.f32 "        \
                 "{%0,%1,%2,%3}, {%4,%5,%6,%7}, {%8,%9}, {%0,%1,%2,%3};\n"   \
                 : "+f"(d[0]), "+f"(d[1]), "+f"(d[2]), "+f"(d[3])            \
                 : "r"(a[0]), "r"(a[1]), "r"(a[2]), "r"(a[3]),               \
                   "r"(b0), "r"(b1))

__device__ __forceinline__ void split_pack_f16(float v0, float v1, uint32_t& hi, uint32_t& lo) {
    __half h0 = __float2half_rn(v0);
    __half h1 = __float2half_rn(v1);
    __half l0 = __float2half_rn(v0 - __half2float(h0));
    __half l1 = __float2half_rn(v1 - __half2float(h1));
    hi = (uint32_t)__half_as_ushort(h0) | ((uint32_t)__half_as_ushort(h1) << 16);
    lo = (uint32_t)__half_as_ushort(l0) | ((uint32_t)__half_as_ushort(l1) << 16);
}

__device__ __forceinline__ uint32_t pack_f16(float v0, float v1) {
    __half h0 = __float2half_rn(v0);
    __half h1 = __float2half_rn(v1);
    return (uint32_t)__half_as_ushort(h0) | ((uint32_t)__half_as_ushort(h1) << 16);
}

template<int LOGC>
__global__ __launch_bounds__(256) void f16_gemm_scores_kernel(
        const float* __restrict__ A, const float* __restrict__ B,
        __half2* __restrict__ C16,
        const float* __restrict__ asrc, const float* __restrict__ adst,
        float* __restrict__ esrc, float* __restrict__ edst,
        int M, int K, int N) {
    __shared__ uint32_t As_hi[2][128 * 9];
    __shared__ uint32_t As_lo[2][128 * 9];
    __shared__ uint32_t Bs_hi[2][128 * 9];

    const int tid  = threadIdx.x;
    const int warp = tid >> 5, lane = tid & 31;
    const int g = lane >> 2, tg = lane & 3;
    const int wy = warp & 3;
    const int wx = warp >> 2;
    const int bm = blockIdx.y * 128, bn = blockIdx.x * 128;

    const int ar = tid >> 1;
    const int ac = (tid & 1) * 8;
    const int kp = warp;
    const int n0 = lane * 4;

    float acc[2][8][4];
#pragma unroll
    for (int mt = 0; mt < 2; mt++)
#pragma unroll
        for (int nt = 0; nt < 8; nt++)
#pragma unroll
            for (int c = 0; c < 4; c++) acc[mt][nt][c] = 0.f;

    const int T = K >> 4;
    const bool arow_ok = (bm + ar) < M;

    float4 a0v, a1v, b0v, b1v;
    if (arow_ok) {
        a0v = *(const float4*)(A + (size_t)(bm + ar) * K + ac);
        a1v = *(const float4*)(A + (size_t)(bm + ar) * K + ac + 4);
    } else {
        a0v = a1v = make_float4(0.f, 0.f, 0.f, 0.f);
    }
    b0v = *(const float4*)(B + (size_t)(2 * kp) * N + bn + n0);
    b1v = *(const float4*)(B + (size_t)(2 * kp + 1) * N + bn + n0);
    {
        const int buf = 0;
        const float* a0p = &a0v.x;
        const float* a1p = &a1v.x;
#pragma unroll
        for (int j = 0; j < 2; j++) {
            uint32_t h, l;
            split_pack_f16(a0p[2 * j], a0p[2 * j + 1], h, l);
            As_hi[buf][ar * 9 + (ac >> 1) + j] = h;
            As_lo[buf][ar * 9 + (ac >> 1) + j] = l;
            split_pack_f16(a1p[2 * j], a1p[2 * j + 1], h, l);
            As_hi[buf][ar * 9 + (ac >> 1) + 2 + j] = h;
            As_lo[buf][ar * 9 + (ac >> 1) + 2 + j] = l;
        }
        const float* b0p = &b0v.x;
        const float* b1p = &b1v.x;
#pragma unroll
        for (int j = 0; j < 4; j++)
            Bs_hi[buf][(n0 + j) * 9 + kp] = pack_f16(b0p[j], b1p[j]);
    }
    __syncthreads();

    for (int t = 0; t < T; t++) {
        const int buf = t & 1;
        if (t + 1 < T) {
            int k0 = (t + 1) << 4;
            if (arow_ok) {
                a0v = *(const float4*)(A + (size_t)(bm + ar) * K + k0 + ac);
                a1v = *(const float4*)(A + (size_t)(bm + ar) * K + k0 + ac + 4);
            }
            b0v = *(const float4*)(B + (size_t)(k0 + 2 * kp) * N + bn + n0);
            b1v = *(const float4*)(B + (size_t)(k0 + 2 * kp + 1) * N + bn + n0);
        }

        uint32_t ah[2][4], al[2][4];
#pragma unroll
        for (int mt = 0; mt < 2; mt++) {
            int r0 = (wy * 32 + mt * 16 + g) * 9 + tg;
            int r1 = r0 + 8 * 9;
            ah[mt][0] = As_hi[buf][r0];
            ah[mt][1] = As_hi[buf][r1];
            ah[mt][2] = As_hi[buf][r0 + 4];
            ah[mt][3] = As_hi[buf][r1 + 4];
            al[mt][0] = As_lo[buf][r0];
            al[mt][1] = As_lo[buf][r1];
            al[mt][2] = As_lo[buf][r0 + 4];
            al[mt][3] = As_lo[buf][r1 + 4];
        }
#pragma unroll
        for (int nt = 0; nt < 8; nt++) {
            int ni = (wx * 64 + nt * 8 + g) * 9 + tg;
            uint32_t bh0 = Bs_hi[buf][ni];
            uint32_t bh1 = Bs_hi[buf][ni + 4];
#pragma unroll
            for (int mt = 0; mt < 2; mt++) {
                MMA_F16(acc[mt][nt], ah[mt], bh0, bh1);
                MMA_F16(acc[mt][nt], al[mt], bh0, bh1);
            }
        }

        if (t + 1 < T) {
            const int nbuf = (t + 1) & 1;
            const float* a0p = &a0v.x;
            const float* a1p = &a1v.x;
#pragma unroll
            for (int j = 0; j < 2; j++) {
                uint32_t h, l;
                split_pack_f16(a0p[2 * j], a0p[2 * j + 1], h, l);
                As_hi[nbuf][ar * 9 + (ac >> 1) + j] = h;
                As_lo[nbuf][ar * 9 + (ac >> 1) + j] = l;
                split_pack_f16(a1p[2 * j], a1p[2 * j + 1], h, l);
                As_hi[nbuf][ar * 9 + (ac >> 1) + 2 + j] = h;
                As_lo[nbuf][ar * 9 + (ac >> 1) + 2 + j] = l;
            }
            const float* b0p = &b0v.x;
            const float* b1p = &b1v.x;
#pragma unroll
            for (int j = 0; j < 4; j++)
                Bs_hi[nbuf][(n0 + j) * 9 + kp] = pack_f16(b0p[j], b1p[j]);
        }
        __syncthreads();
    }

    // ---- epilogue 1: write C as fp16 ----
#pragma unroll
    for (int mt = 0; mt < 2; mt++) {
        int gr0 = bm + wy * 32 + mt * 16 + g;
        int gr1 = gr0 + 8;
#pragma unroll
        for (int nt = 0; nt < 8; nt++) {
            int col = bn + wx * 64 + nt * 8 + 2 * tg;
            if (gr0 < M)
                C16[((size_t)gr0 * N + col) >> 1] =
                    __floats2half2_rn(acc[mt][nt][0], acc[mt][nt][1]);
            if (gr1 < M)
                C16[((size_t)gr1 * N + col) >> 1] =
                    __floats2half2_rn(acc[mt][nt][2], acc[mt][nt][3]);
        }
    }

    // ---- epilogue 2: fused attention scores ----
    const int NSLOT = (LOGC == 6) ? 1 : 2;
    float psrc[2][2][2] = {};
    float pdst[2][2][2] = {};
#pragma unroll
    for (int nt = 0; nt < 8; nt++) {
        int gc = bn + wx * 64 + nt * 8 + 2 * tg;
        float2 as = *(const float2*)&asrc[gc];
        float2 ad = *(const float2*)&adst[gc];
        int hs = (LOGC == 6) ? 0 : (nt >> 2);
#pragma unroll
        for (int mt = 0; mt < 2; mt++) {
            psrc[mt][0][hs] += acc[mt][nt][0] * as.x + acc[mt][nt][1] * as.y;
            psrc[mt][1][hs] += acc[mt][nt][2] * as.x + acc[mt][nt][3] * as.y;
            pdst[mt][0][hs] += acc[mt][nt][0] * ad.x + acc[mt][nt][1] * ad.y;
            pdst[mt][1][hs] += acc[mt][nt][2] * ad.x + acc[mt][nt][3] * ad.y;
        }
    }
#pragma unroll
    for (int mt = 0; mt < 2; mt++)
#pragma unroll
        for (int rh = 0; rh < 2; rh++)
#pragma unroll
            for (int hs = 0; hs < NSLOT; hs++) {
                float s1 = psrc[mt][rh][hs], s2 = pdst[mt][rh][hs];
                s1 += __shfl_xor_sync(0xffffffffu, s1, 1);
                s1 += __shfl_xor_sync(0xffffffffu, s1, 2);
                s2 += __shfl_xor_sync(0xffffffffu, s2, 1);
                s2 += __shfl_xor_sync(0xffffffffu, s2, 2);
                psrc[mt][rh][hs] = s1;
                pdst[mt][rh][hs] = s2;
            }
    if (tg == 0) {
#pragma unroll
        for (int mt = 0; mt < 2; mt++)
#pragma unroll
            for (int rh = 0; rh < 2; rh++) {
                int gr = bm + wy * 32 + mt * 16 + g + rh * 8;
                if (gr < M) {
#pragma unroll
                    for (int hs = 0; hs < NSLOT; hs++) {
                        int hd = (LOGC == 6) ? ((bn >> 6) + wx) : (wx * 2 + hs);
                        esrc[gr * 4 + hd] = psrc[mt][rh][hs];
                        edst[gr * 4 + hd] = pdst[mt][rh][hs];
                    }
                }
            }
    }
}

// ---------------- fused aggregation: warp per dst node -----------------------
// Lane owns HPL consecutive halves (HPL=8 for HC=256, 4 for HC=128); head of a
// lane = lane>>3 in both cases. Per 32-edge tile: stage p0..3 + src in smem,
// then inner loop does 1 broadcast LDS (own-head weight) + 1 wide LDG per lane.
template<int HPL, int DOELU>
__global__ __launch_bounds__(256) void gat_agg_kernel(
        const __half2* __restrict__ h16,
        const float* __restrict__ esrc, const float* __restrict__ edst,
        const int* __restrict__ off, const int* __restrict__ csr_src,
        const float* __restrict__ bias,
        const float* __restrict__ gam, const float* __restrict__ bet,
        float* __restrict__ outp, int Nn) {
    const int HC  = HPL * 32;
    const int HC2 = HPL * 16;      // half2 words per node
    __shared__ float sp[8][32][4];
    __shared__ int   si[8][32];

    int wslot = threadIdx.x >> 5;
    int n = (blockIdx.x * blockDim.x + threadIdx.x) >> 5;
    int lane = threadIdx.x & 31;
    if (n >= Nn) return;
    int hd = lane >> 3;

    int beg = off[n], end = off[n + 1];
    float4 ed = ((const float4*)edst)[n];

    // pass 1: segment max per head
    float m0 = -INFINITY, m1 = -INFINITY, m2 = -INFINITY, m3 = -INFINITY;
    for (int i = beg + lane; i < end; i += 32) {
        int s = csr_src[i];
        float4 es = ((const float4*)esrc)[s];
        float e0 = es.x + ed.x; e0 = e0 > 0.f ? e0 : SLOPE * e0; m0 = fmaxf(m0, e0);
        float e1 = es.y + ed.y; e1 = e1 > 0.f ? e1 : SLOPE * e1; m1 = fmaxf(m1, e1);
        float e2 = es.z + ed.z; e2 = e2 > 0.f ? e2 : SLOPE * e2; m2 = fmaxf(m2, e2);
        float e3 = es.w + ed.w; e3 = e3 > 0.f ? e3 : SLOPE * e3; m3 = fmaxf(m3, e3);
    }
#pragma unroll
    for (int d = 16; d > 0; d >>= 1) {
        m0 = fmaxf(m0, __shfl_xor_sync(0xffffffffu, m0, d));
        m1 = fmaxf(m1, __shfl_xor_sync(0xffffffffu, m1, d));
        m2 = fmaxf(m2, __shfl_xor_sync(0xffffffffu, m2, d));
        m3 = fmaxf(m3, __shfl_xor_sync(0xffffffffu, m3, d));
    }

    // pass 2
    float acc[HPL];
#pragma unroll
    for (int j = 0; j < HPL; j++) acc[j] = 0.f;
    float den = 0.f;

    for (int i = beg; i < end; i += 32) {
        int cnt = min(32, end - i);
        int s_l = 0;
        float p0 = 0.f, p1 = 0.f, p2 = 0.f, p3 = 0.f;
        if (lane < cnt) {
            s_l = csr_src[i + lane];
            float4 es = ((const float4*)esrc)[s_l];
            float e0 = es.x + ed.x; e0 = e0 > 0.f ? e0 : SLOPE * e0;
            float e1 = es.y + ed.y; e1 = e1 > 0.f ? e1 : SLOPE * e1;
            float e2 = es.z + ed.z; e2 = e2 > 0.f ? e2 : SLOPE * e2;
            float e3 = es.w + ed.w; e3 = e3 > 0.f ? e3 : SLOPE * e3;
            p0 = __expf(e0 - m0); p1 = __expf(e1 - m1);
            p2 = __expf(e2 - m2); p3 = __expf(e3 - m3);
        }
        si[wslot][lane] = s_l;
        *(float4*)&sp[wslot][lane][0] = make_float4(p0, p1, p2, p3);
        __syncwarp();

#pragma unroll 4
        for (int k = 0; k < cnt; k++) {
            int   ss = si[wslot][k];
            float q  = sp[wslot][k][hd];
            den += q;
            const uint32_t* rp = (const uint32_t*)(h16 + (size_t)ss * HC2);
            uint32_t w[4];
            if (HPL == 8) {
                uint4 v = ((const uint4*)rp)[lane];
                w[0] = v.x; w[1] = v.y; w[2] = v.z; w[3] = v.w;
            } else {
                uint2 v = ((const uint2*)rp)[lane];
                w[0] = v.x; w[1] = v.y; w[2] = 0; w[3] = 0;
            }
#pragma unroll
            for (int j = 0; j < HPL / 2; j++) {
                float2 f = __half22float2(*(const __half2*)&w[j]);
                acc[2 * j]     += q * f.x;
                acc[2 * j + 1] += q * f.y;
            }
        }
        __syncwarp();
    }

    // epilogue: /den, +bias, (ELU), LayerNorm — all coalesced float4
    int fb = lane * HPL;
    float vals[HPL];
    float sum = 0.f;
#pragma unroll
    for (int j = 0; j < HPL; j += 4) {
        float4 b = *(const float4*)&bias[fb + j];
        float v0 = acc[j]     / den + b.x;
        float v1 = acc[j + 1] / den + b.y;
        float v2 = acc[j + 2] / den + b.z;
        float v3 = acc[j + 3] / den + b.w;
        if (DOELU) {
            v0 = v0 > 0.f ? v0 : expm1f(v0);
            v1 = v1 > 0.f ? v1 : expm1f(v1);
            v2 = v2 > 0.f ? v2 : expm1f(v2);
            v3 = v3 > 0.f ? v3 : expm1f(v3);
        }
        vals[j] = v0; vals[j + 1] = v1; vals[j + 2] = v2; vals[j + 3] = v3;
        sum += v0 + v1 + v2 + v3;
    }
#pragma unroll
    for (int d = 16; d > 0; d >>= 1) sum += __shfl_xor_sync(0xffffffffu, sum, d);
    float mu = sum / (float)HC;
    float vs = 0.f;
#pragma unroll
    for (int j = 0; j < HPL; j++) {
        float dv = vals[j] - mu;
        vs += dv * dv;
    }
#pragma unroll
    for (int d = 16; d > 0; d >>= 1) vs += __shfl_xor_sync(0xffffffffu, vs, d);
    float rstd = rsqrtf(vs / (float)HC + LN_EPS);
#pragma unroll
    for (int j = 0; j < HPL; j += 4) {
        float4 gm = *(const float4*)&gam[fb + j];
        float4 bt = *(const float4*)&bet[fb + j];
        float4 o;
        o.x = gm.x * (vals[j]     - mu) * rstd + bt.x;
        o.y = gm.y * (vals[j + 1] - mu) * rstd + bt.y;
        o.z = gm.z * (vals[j + 2] - mu) * rstd + bt.z;
        o.w = gm.w * (vals[j + 3] - mu) * rstd + bt.w;
        *(float4*)&outp[(size_t)n * HC + fb + j] = o;
    }
}

// ---------------- mean pool: block per graph, binary search (batch sorted) ---
__global__ void pool_kernel(const float* __restrict__ node_out, const int* __restrict__ batch,
                            float* __restrict__ graph_out, int Nn) {
    int g = blockIdx.x;
    int f = threadIdx.x;  // 128
    int lo = 0, hi = Nn;
    while (lo < hi) { int mid = (lo + hi) >> 1; if (batch[mid] < g) lo = mid + 1; else hi = mid; }
    int start = lo;
    lo = start; hi = Nn;
    while (lo < hi) { int mid = (lo + hi) >> 1; if (batch[mid] < g + 1) lo = mid + 1; else hi = mid; }
    int end = lo;
    float s = 0.f;
    for (int n = start; n < end; n++) s += node_out[(size_t)n * 128 + f];
    graph_out[g * 128 + f] = s / fmaxf((float)(end - start), 1.f);
}

// ---------------- launch -----------------------------------------------------
extern "C" void kernel_launch(void* const* d_in, const int* in_sizes, int n_in,
                              void* d_out, int out_size) {
    const float* x     = (const float*)d_in[0];
    const int*   ei    = (const int*)d_in[1];
    const int*   batch = (const int*)d_in[2];
    const float* W[3]    = {(const float*)d_in[3],  (const float*)d_in[9],  (const float*)d_in[15]};
    const float* asrc[3] = {(const float*)d_in[4],  (const float*)d_in[10], (const float*)d_in[16]};
    const float* adst[3] = {(const float*)d_in[5],  (const float*)d_in[11], (const float*)d_in[17]};
    const float* bia[3]  = {(const float*)d_in[6],  (const float*)d_in[12], (const float*)d_in[18]};
    const float* gam[3]  = {(const float*)d_in[7],  (const float*)d_in[13], (const float*)d_in[19]};
    const float* bet[3]  = {(const float*)d_in[8],  (const float*)d_in[14], (const float*)d_in[20]};

    int N = in_sizes[0] / 768;
    int E = in_sizes[1] / 2;
    int Etot = E + N;
    const int* srcA = ei;
    const int* dstA = ei + E;

    float* node_out  = (float*)d_out;
    float* graph_out = node_out + (size_t)N * 128;

    __half2* p_h16;
    float *p_in, *p_esrc, *p_edst;
    int *p_deg, *p_off, *p_cur, *p_csr;
    cudaGetSymbolAddress((void**)&p_h16, g_h16_raw);
    cudaGetSymbolAddress((void**)&p_in, g_in);
    cudaGetSymbolAddress((void**)&p_esrc, g_esrc);
    cudaGetSymbolAddress((void**)&p_edst, g_edst);
    cudaGetSymbolAddress((void**)&p_deg, g_deg);
    cudaGetSymbolAddress((void**)&p_off, g_off);
    cudaGetSymbolAddress((void**)&p_cur, g_cur);
    cudaGetSymbolAddress((void**)&p_csr, g_csr);

    // ---- build dst-CSR once (shared across all 3 layers) ----
    init_deg_kernel<<<(N + 255) / 256, 256>>>(p_deg, p_cur, N);
    deg_hist_kernel<<<(E + 255) / 256, 256>>>(dstA, E, p_deg);
    scan_kernel<<<1, 1024>>>(p_deg, p_off, N);
    csr_scatter_kernel<<<(Etot + 255) / 256, 256>>>(srcA, dstA, E, Etot, p_off, p_cur, p_csr);

    int dins[3] = {768, 256, 256};
    int HCs[3]  = {256, 256, 128};
    const float* inputs[3] = {x, p_in, p_in};
    float* outs[3] = {p_in, p_in, node_out};

    for (int L = 0; L < 3; L++) {
        int K = dins[L], HC = HCs[L];

        dim3 ggrid(HC / 128, (N + 127) / 128);
        int nwb = (N + 7) / 8;   // 8 warps / block for agg

        if (HC == 256) {
            f16_gemm_scores_kernel<6><<<ggrid, 256>>>(inputs[L], W[L], p_h16,
                                                      asrc[L], adst[L], p_esrc, p_edst,
                                                      N, K, HC);
            if (L < 2)
                gat_agg_kernel<8, 1><<<nwb, 256>>>(p_h16, p_esrc, p_edst, p_off, p_csr,
                                                   bia[L], gam[L], bet[L], outs[L], N);
            else
                gat_agg_kernel<8, 0><<<nwb, 256>>>(p_h16, p_esrc, p_edst, p_off, p_csr,
                                                   bia[L], gam[L], bet[L], outs[L], N);
        } else {
            f16_gemm_scores_kernel<5><<<ggrid, 256>>>(inputs[L], W[L], p_h16,
                                                      asrc[L], adst[L], p_esrc, p_edst,
                                                      N, K, HC);
            gat_agg_kernel<4, 0><<<nwb, 256>>>(p_h16, p_esrc, p_edst, p_off, p_csr,
                                               bia[L], gam[L], bet[L], outs[L], N);
        }
    }

    pool_kernel<<<GMAX, 128>>>(node_out, batch, graph_out, N);
}